// round 1
// baseline (speedup 1.0000x reference)
#include <cuda_runtime.h>

// Problem constants
#define B_   16
#define D_   512
#define L_   3000
#define NE_  1024

// Tiling
#define LT   128   // l-columns per block
#define NT   128   // codebook rows per n-tile
#define KC   32    // k chunk staged in smem

// Output layout (flattened tuple): z_q [B*D*L] fp32, ind [B*L] (as fp32), diff [1]
#define ZQ_ELEMS   ((size_t)B_ * D_ * L_)
#define IND_ELEMS  ((size_t)B_ * L_)

__device__ double g_loss;

__global__ void init_loss_kernel() { g_loss = 0.0; }

__global__ void finalize_kernel(float* __restrict__ out) {
    // quant_loss = mean((zq-z)^2) + mean((zq_hard-z)^2) + 0.25*mean((zq_hard-z)^2)
    //            = 2.25 * mean  (since zq == zq_hard in forward values)
    out[ZQ_ELEMS + IND_ELEMS] = (float)(2.25 * g_loss / ((double)B_ * D_ * L_));
}

__global__ __launch_bounds__(256, 2)
void vq_argmax_kernel(const float* __restrict__ z,
                      const float* __restrict__ W,
                      float* __restrict__ out)
{
    // Ws region is reused for the argmax reduction scratch after each n-tile.
    __shared__ union SA {
        float Ws[KC][NT];                                  // 16 KB
        struct { float rmax[16][LT]; int ridx[16][LT]; } red; // 16 KB
    } sA;
    __shared__ float Zs[KC][LT];                           // 16 KB
    __shared__ float bestv[LT];
    __shared__ int   besti[LT];
    __shared__ double lred[256];

    const int tid = threadIdx.x;
    const int tx  = tid & 15;   // l-group (8 cols each)
    const int ty  = tid >> 4;   // n-group (8 rows each)
    const int b   = blockIdx.y;
    const int lb  = blockIdx.x * LT;

    if (tid < LT) {
        bestv[tid] = __int_as_float(0xff800000);  // -inf
        besti[tid] = 0;
    }

    const float* zb = z + (size_t)b * D_ * L_;

    for (int nt = 0; nt < NE_ / NT; ++nt) {
        const int nb = nt * NT;

        float acc[8][8];
        #pragma unroll
        for (int i = 0; i < 8; ++i)
            #pragma unroll
            for (int j = 0; j < 8; ++j) acc[i][j] = 0.0f;

        for (int kc = 0; kc < D_ / KC; ++kc) {
            const int kb = kc * KC;
            __syncthreads();  // protect smem from previous phase consumers

            // Load W tile: NT(128) rows x KC(32) k  -> Ws[k][n]
            // 1024 float4 total, 4 per thread. Coalesced along k.
            #pragma unroll
            for (int p = 0; p < 4; ++p) {
                int v  = tid + p * 256;
                int n  = v >> 3;      // 0..127
                int kq = v & 7;       // which float4 within 32 k
                float4 wv = *reinterpret_cast<const float4*>(
                    &W[(size_t)(nb + n) * D_ + kb + kq * 4]);
                sA.Ws[kq * 4 + 0][n] = wv.x;
                sA.Ws[kq * 4 + 1][n] = wv.y;
                sA.Ws[kq * 4 + 2][n] = wv.z;
                sA.Ws[kq * 4 + 3][n] = wv.w;
            }
            // Load Z tile: KC(32) k x LT(128) l -> Zs[k][l]. Coalesced along l.
            #pragma unroll
            for (int p = 0; p < 4; ++p) {
                int v  = tid + p * 256;
                int l4 = v & 31;
                int k  = v >> 5;
                int l  = lb + l4 * 4;
                float4 zv = make_float4(0.f, 0.f, 0.f, 0.f);
                if (l < L_)
                    zv = *reinterpret_cast<const float4*>(
                        &zb[(size_t)(kb + k) * L_ + l]);
                *reinterpret_cast<float4*>(&Zs[k][l4 * 4]) = zv;
            }
            __syncthreads();

            #pragma unroll
            for (int k = 0; k < KC; ++k) {
                float wf[8], zf[8];
                #pragma unroll
                for (int i = 0; i < 8; ++i) wf[i] = sA.Ws[k][ty * 8 + i];
                #pragma unroll
                for (int j = 0; j < 8; ++j) zf[j] = Zs[k][tx * 8 + j];
                #pragma unroll
                for (int i = 0; i < 8; ++i)
                    #pragma unroll
                    for (int j = 0; j < 8; ++j)
                        acc[i][j] = fmaf(wf[i], zf[j], acc[i][j]);
            }
        }
        __syncthreads();  // all compute done, safe to overwrite Ws with red

        // Per-thread max over its 8 rows, for each of its 8 columns.
        #pragma unroll
        for (int j = 0; j < 8; ++j) {
            float m = acc[0][j];
            int   mi = nb + ty * 8;
            #pragma unroll
            for (int i = 1; i < 8; ++i) {
                float v = acc[i][j];
                if (v > m) { m = v; mi = nb + ty * 8 + i; }
            }
            sA.red.rmax[ty][tx * 8 + j] = m;
            sA.red.ridx[ty][tx * 8 + j] = mi;
        }
        __syncthreads();

        // Column owners (tid<128) fold the 16 partials into the running best.
        if (tid < LT) {
            float m  = bestv[tid];
            int   mi = besti[tid];
            #pragma unroll
            for (int r = 0; r < 16; ++r) {
                float v  = sA.red.rmax[r][tid];
                int   vi = sA.red.ridx[r][tid];
                if (v > m || (v == m && vi < mi)) { m = v; mi = vi; }
            }
            bestv[tid] = m;
            besti[tid] = mi;
        }
        // next nt's leading __syncthreads() protects the red region
    }
    __syncthreads();

    // ---- Epilogue: gather codebook rows, write z_q, ind, accumulate loss ----
    const int valid = (L_ - lb < LT) ? (L_ - lb) : LT;
    double lsum = 0.0;

    // 128 cols x 512 d = 65536 elems, 256 per thread; col fastest -> coalesced
    #pragma unroll 4
    for (int p = 0; p < (LT * D_) / 256; ++p) {
        int idx = p * 256 + tid;
        int col = idx & (LT - 1);
        int d   = idx >> 7;
        if (col < valid) {
            int l = lb + col;
            float wv = W[(size_t)besti[col] * D_ + d];
            float zv = zb[(size_t)d * L_ + l];
            out[((size_t)b * D_ + d) * L_ + l] = wv;
            float df = wv - zv;
            lsum += (double)df * (double)df;
        }
    }

    if (tid < valid) {
        out[ZQ_ELEMS + (size_t)b * L_ + lb + tid] = (float)besti[tid];
    }

    lred[tid] = lsum;
    __syncthreads();
    #pragma unroll
    for (int s = 128; s > 0; s >>= 1) {
        if (tid < s) lred[tid] += lred[tid + s];
        __syncthreads();
    }
    if (tid == 0) atomicAdd(&g_loss, lred[0]);
}

extern "C" void kernel_launch(void* const* d_in, const int* in_sizes, int n_in,
                              void* d_out, int out_size) {
    const float* z = (const float*)d_in[0];
    const float* W = (const float*)d_in[1];
    // Defensive: identify tensors by size (z has B*D*L, W has NE*D elems)
    if (n_in >= 2 && in_sizes[0] == NE_ * D_) {
        z = (const float*)d_in[1];
        W = (const float*)d_in[0];
    }
    float* out = (float*)d_out;

    init_loss_kernel<<<1, 1>>>();
    dim3 grid((L_ + LT - 1) / LT, B_);
    vq_argmax_kernel<<<grid, 256>>>(z, W, out);
    finalize_kernel<<<1, 1>>>(out);
}

// round 2
// speedup vs baseline: 1.3689x; 1.3689x over previous
#include <cuda_runtime.h>

// Problem constants
#define B_   16
#define D_   512
#define L_   3000
#define NE_  1024

// Tiling
#define LT   128   // l-columns per block
#define NT   128   // codebook rows per n-tile
#define KC   32    // k chunk staged in smem

// Output layout (flattened tuple): z_q [B*D*L] fp32, ind [B*L] (as fp32), diff [1]
#define ZQ_ELEMS   ((size_t)B_ * D_ * L_)
#define IND_ELEMS  ((size_t)B_ * L_)

__device__ double g_loss;

__global__ void init_loss_kernel() { g_loss = 0.0; }

__global__ void finalize_kernel(float* __restrict__ out) {
    // quant_loss = mean((zq-z)^2) + mean((zq_hard-z)^2) + 0.25*mean((zq_hard-z)^2)
    //            = 2.25 * mean  (since zq == zq_hard in forward values)
    out[ZQ_ELEMS + IND_ELEMS] = (float)(2.25 * g_loss / ((double)B_ * D_ * L_));
}

__global__ __launch_bounds__(256, 2)
void vq_argmax_kernel(const float* __restrict__ z,
                      const float* __restrict__ W,
                      float* __restrict__ out)
{
    // Ws region is reused for the argmax reduction scratch after each n-tile.
    __shared__ union SA {
        float Ws[KC][NT];                                  // 16 KB
        struct { float rmax[16][LT]; int ridx[16][LT]; } red; // 16 KB
    } sA;
    __shared__ float Zs[KC][LT];                           // 16 KB
    __shared__ float bestv[LT];
    __shared__ int   besti[LT];
    __shared__ double lred[256];

    const int tid = threadIdx.x;
    const int tx  = tid & 15;   // l-group (8 cols each)
    const int ty  = tid >> 4;   // n-group (8 rows each)
    const int b   = blockIdx.y;
    const int lb  = blockIdx.x * LT;

    if (tid < LT) {
        bestv[tid] = __int_as_float(0xff800000);  // -inf
        besti[tid] = 0;
    }

    const float* zb = z + (size_t)b * D_ * L_;

    for (int nt = 0; nt < NE_ / NT; ++nt) {
        const int nb = nt * NT;

        float acc[8][8];
        #pragma unroll
        for (int i = 0; i < 8; ++i)
            #pragma unroll
            for (int j = 0; j < 8; ++j) acc[i][j] = 0.0f;

        for (int kc = 0; kc < D_ / KC; ++kc) {
            const int kb = kc * KC;
            __syncthreads();  // protect smem from previous phase consumers

            // Load W tile: NT(128) rows x KC(32) k  -> Ws[k][n]
            // 1024 float4 total, 4 per thread. Coalesced along k.
            #pragma unroll
            for (int p = 0; p < 4; ++p) {
                int v  = tid + p * 256;
                int n  = v >> 3;      // 0..127
                int kq = v & 7;       // which float4 within 32 k
                float4 wv = *reinterpret_cast<const float4*>(
                    &W[(size_t)(nb + n) * D_ + kb + kq * 4]);
                sA.Ws[kq * 4 + 0][n] = wv.x;
                sA.Ws[kq * 4 + 1][n] = wv.y;
                sA.Ws[kq * 4 + 2][n] = wv.z;
                sA.Ws[kq * 4 + 3][n] = wv.w;
            }
            // Load Z tile: KC(32) k x LT(128) l -> Zs[k][l]. Coalesced along l.
            #pragma unroll
            for (int p = 0; p < 4; ++p) {
                int v  = tid + p * 256;
                int l4 = v & 31;
                int k  = v >> 5;
                int l  = lb + l4 * 4;
                float4 zv = make_float4(0.f, 0.f, 0.f, 0.f);
                if (l < L_)
                    zv = *reinterpret_cast<const float4*>(
                        &zb[(size_t)(kb + k) * L_ + l]);
                *reinterpret_cast<float4*>(&Zs[k][l4 * 4]) = zv;
            }
            __syncthreads();

            #pragma unroll
            for (int k = 0; k < KC; ++k) {
                float wf[8], zf[8];
                #pragma unroll
                for (int i = 0; i < 8; ++i) wf[i] = sA.Ws[k][ty * 8 + i];
                #pragma unroll
                for (int j = 0; j < 8; ++j) zf[j] = Zs[k][tx * 8 + j];
                #pragma unroll
                for (int i = 0; i < 8; ++i)
                    #pragma unroll
                    for (int j = 0; j < 8; ++j)
                        acc[i][j] = fmaf(wf[i], zf[j], acc[i][j]);
            }
        }
        __syncthreads();  // all compute done, safe to overwrite Ws with red

        // Per-thread max over its 8 rows, for each of its 8 columns.
        #pragma unroll
        for (int j = 0; j < 8; ++j) {
            float m = acc[0][j];
            int   mi = nb + ty * 8;
            #pragma unroll
            for (int i = 1; i < 8; ++i) {
                float v = acc[i][j];
                if (v > m) { m = v; mi = nb + ty * 8 + i; }
            }
            sA.red.rmax[ty][tx * 8 + j] = m;
            sA.red.ridx[ty][tx * 8 + j] = mi;
        }
        __syncthreads();

        // Column owners (tid<128) fold the 16 partials into the running best.
        if (tid < LT) {
            float m  = bestv[tid];
            int   mi = besti[tid];
            #pragma unroll
            for (int r = 0; r < 16; ++r) {
                float v  = sA.red.rmax[r][tid];
                int   vi = sA.red.ridx[r][tid];
                if (v > m || (v == m && vi < mi)) { m = v; mi = vi; }
            }
            bestv[tid] = m;
            besti[tid] = mi;
        }
        // next nt's leading __syncthreads() protects the red region
    }
    __syncthreads();

    // ---- Epilogue: gather codebook rows, write z_q, ind, accumulate loss ----
    const int valid = (L_ - lb < LT) ? (L_ - lb) : LT;
    double lsum = 0.0;

    // 128 cols x 512 d = 65536 elems, 256 per thread; col fastest -> coalesced
    #pragma unroll 4
    for (int p = 0; p < (LT * D_) / 256; ++p) {
        int idx = p * 256 + tid;
        int col = idx & (LT - 1);
        int d   = idx >> 7;
        if (col < valid) {
            int l = lb + col;
            float wv = W[(size_t)besti[col] * D_ + d];
            float zv = zb[(size_t)d * L_ + l];
            out[((size_t)b * D_ + d) * L_ + l] = wv;
            float df = wv - zv;
            lsum += (double)df * (double)df;
        }
    }

    if (tid < valid) {
        out[ZQ_ELEMS + (size_t)b * L_ + lb + tid] = (float)besti[tid];
    }

    lred[tid] = lsum;
    __syncthreads();
    #pragma unroll
    for (int s = 128; s > 0; s >>= 1) {
        if (tid < s) lred[tid] += lred[tid + s];
        __syncthreads();
    }
    if (tid == 0) atomicAdd(&g_loss, lred[0]);
}

extern "C" void kernel_launch(void* const* d_in, const int* in_sizes, int n_in,
                              void* d_out, int out_size) {
    const float* z = (const float*)d_in[0];
    const float* W = (const float*)d_in[1];
    // Defensive: identify tensors by size (z has B*D*L, W has NE*D elems)
    if (n_in >= 2 && in_sizes[0] == NE_ * D_) {
        z = (const float*)d_in[1];
        W = (const float*)d_in[0];
    }
    float* out = (float*)d_out;

    init_loss_kernel<<<1, 1>>>();
    dim3 grid((L_ + LT - 1) / LT, B_);
    vq_argmax_kernel<<<grid, 256>>>(z, W, out);
    finalize_kernel<<<1, 1>>>(out);
}

// round 3
// speedup vs baseline: 1.3732x; 1.0031x over previous
#include <cuda_runtime.h>

// Problem constants
#define B_   16
#define D_   512
#define L_   3000
#define NE_  1024

// Tiling
#define LT   128   // l-columns per block
#define NT   128   // codebook rows per n-tile
#define KC   32    // k chunk staged in smem

// Output layout (flattened tuple): z_q [B*D*L] fp32, ind [B*L] (as fp32), diff [1]
#define ZQ_ELEMS   ((size_t)B_ * D_ * L_)
#define IND_ELEMS  ((size_t)B_ * L_)

__device__ double g_loss;

__global__ void init_loss_kernel() { g_loss = 0.0; }

__global__ void finalize_kernel(float* __restrict__ out) {
    // quant_loss = mean((zq-z)^2) + mean((zq_hard-z)^2) + 0.25*mean((zq_hard-z)^2)
    //            = 2.25 * mean  (since zq == zq_hard in forward values)
    out[ZQ_ELEMS + IND_ELEMS] = (float)(2.25 * g_loss / ((double)B_ * D_ * L_));
}

__global__ __launch_bounds__(256, 2)
void vq_argmax_kernel(const float* __restrict__ z,
                      const float* __restrict__ W,
                      float* __restrict__ out)
{
    // Ws region is reused for the argmax reduction scratch after each n-tile.
    __shared__ union SA {
        float Ws[KC][NT];                                  // 16 KB
        struct { float rmax[16][LT]; int ridx[16][LT]; } red; // 16 KB
    } sA;
    __shared__ float Zs[KC][LT];                           // 16 KB
    __shared__ float bestv[LT];
    __shared__ int   besti[LT];
    __shared__ double lred[256];

    const int tid = threadIdx.x;
    const int tx  = tid & 15;   // l-group (8 cols each)
    const int ty  = tid >> 4;   // n-group (8 rows each)
    const int b   = blockIdx.y;
    const int lb  = blockIdx.x * LT;

    if (tid < LT) {
        bestv[tid] = __int_as_float(0xff800000);  // -inf
        besti[tid] = 0;
    }

    const float* zb = z + (size_t)b * D_ * L_;

    for (int nt = 0; nt < NE_ / NT; ++nt) {
        const int nb = nt * NT;

        float acc[8][8];
        #pragma unroll
        for (int i = 0; i < 8; ++i)
            #pragma unroll
            for (int j = 0; j < 8; ++j) acc[i][j] = 0.0f;

        for (int kc = 0; kc < D_ / KC; ++kc) {
            const int kb = kc * KC;
            __syncthreads();  // protect smem from previous phase consumers

            // Load W tile: NT(128) rows x KC(32) k  -> Ws[k][n]
            // 1024 float4 total, 4 per thread. Coalesced along k.
            #pragma unroll
            for (int p = 0; p < 4; ++p) {
                int v  = tid + p * 256;
                int n  = v >> 3;      // 0..127
                int kq = v & 7;       // which float4 within 32 k
                float4 wv = *reinterpret_cast<const float4*>(
                    &W[(size_t)(nb + n) * D_ + kb + kq * 4]);
                sA.Ws[kq * 4 + 0][n] = wv.x;
                sA.Ws[kq * 4 + 1][n] = wv.y;
                sA.Ws[kq * 4 + 2][n] = wv.z;
                sA.Ws[kq * 4 + 3][n] = wv.w;
            }
            // Load Z tile: KC(32) k x LT(128) l -> Zs[k][l]. Coalesced along l.
            #pragma unroll
            for (int p = 0; p < 4; ++p) {
                int v  = tid + p * 256;
                int l4 = v & 31;
                int k  = v >> 5;
                int l  = lb + l4 * 4;
                float4 zv = make_float4(0.f, 0.f, 0.f, 0.f);
                if (l < L_)
                    zv = *reinterpret_cast<const float4*>(
                        &zb[(size_t)(kb + k) * L_ + l]);
                *reinterpret_cast<float4*>(&Zs[k][l4 * 4]) = zv;
            }
            __syncthreads();

            #pragma unroll
            for (int k = 0; k < KC; ++k) {
                float wf[8], zf[8];
                #pragma unroll
                for (int i = 0; i < 8; ++i) wf[i] = sA.Ws[k][ty * 8 + i];
                #pragma unroll
                for (int j = 0; j < 8; ++j) zf[j] = Zs[k][tx * 8 + j];
                #pragma unroll
                for (int i = 0; i < 8; ++i)
                    #pragma unroll
                    for (int j = 0; j < 8; ++j)
                        acc[i][j] = fmaf(wf[i], zf[j], acc[i][j]);
            }
        }
        __syncthreads();  // all compute done, safe to overwrite Ws with red

        // Per-thread max over its 8 rows, for each of its 8 columns.
        #pragma unroll
        for (int j = 0; j < 8; ++j) {
            float m = acc[0][j];
            int   mi = nb + ty * 8;
            #pragma unroll
            for (int i = 1; i < 8; ++i) {
                float v = acc[i][j];
                if (v > m) { m = v; mi = nb + ty * 8 + i; }
            }
            sA.red.rmax[ty][tx * 8 + j] = m;
            sA.red.ridx[ty][tx * 8 + j] = mi;
        }
        __syncthreads();

        // Column owners (tid<128) fold the 16 partials into the running best.
        if (tid < LT) {
            float m  = bestv[tid];
            int   mi = besti[tid];
            #pragma unroll
            for (int r = 0; r < 16; ++r) {
                float v  = sA.red.rmax[r][tid];
                int   vi = sA.red.ridx[r][tid];
                if (v > m || (v == m && vi < mi)) { m = v; mi = vi; }
            }
            bestv[tid] = m;
            besti[tid] = mi;
        }
        // next nt's leading __syncthreads() protects the red region
    }
    __syncthreads();

    // ---- Epilogue: gather codebook rows, write z_q, ind, accumulate loss ----
    const int valid = (L_ - lb < LT) ? (L_ - lb) : LT;
    double lsum = 0.0;

    // 128 cols x 512 d = 65536 elems, 256 per thread; col fastest -> coalesced
    #pragma unroll 4
    for (int p = 0; p < (LT * D_) / 256; ++p) {
        int idx = p * 256 + tid;
        int col = idx & (LT - 1);
        int d   = idx >> 7;
        if (col < valid) {
            int l = lb + col;
            float wv = W[(size_t)besti[col] * D_ + d];
            float zv = zb[(size_t)d * L_ + l];
            out[((size_t)b * D_ + d) * L_ + l] = wv;
            float df = wv - zv;
            lsum += (double)df * (double)df;
        }
    }

    if (tid < valid) {
        out[ZQ_ELEMS + (size_t)b * L_ + lb + tid] = (float)besti[tid];
    }

    lred[tid] = lsum;
    __syncthreads();
    #pragma unroll
    for (int s = 128; s > 0; s >>= 1) {
        if (tid < s) lred[tid] += lred[tid + s];
        __syncthreads();
    }
    if (tid == 0) atomicAdd(&g_loss, lred[0]);
}

extern "C" void kernel_launch(void* const* d_in, const int* in_sizes, int n_in,
                              void* d_out, int out_size) {
    const float* z = (const float*)d_in[0];
    const float* W = (const float*)d_in[1];
    // Defensive: identify tensors by size (z has B*D*L, W has NE*D elems)
    if (n_in >= 2 && in_sizes[0] == NE_ * D_) {
        z = (const float*)d_in[1];
        W = (const float*)d_in[0];
    }
    float* out = (float*)d_out;

    init_loss_kernel<<<1, 1>>>();
    dim3 grid((L_ + LT - 1) / LT, B_);
    vq_argmax_kernel<<<grid, 256>>>(z, W, out);
    finalize_kernel<<<1, 1>>>(out);
}

// round 5
// speedup vs baseline: 2.8386x; 2.0672x over previous
#include <cuda_runtime.h>
#include <cstdint>

#define B_    16
#define D_    512
#define L_    3000
#define NE_   1024
#define ZQ_ELEMS  ((size_t)B_ * D_ * L_)
#define IND_ELEMS ((size_t)B_ * L_)

#define DELTA   0.15f
#define CAPROW  49152        // max flagged columns (>= all 48000)
#define NSLICE  8            // rescan code slices of 128
#define RLT     64           // rescan columns per CTA

// ---- device scratch (no allocation allowed anywhere) ----
__device__ int    g_best[B_ * L_];
__device__ int    g_flagcnt;
__device__ int    g_flaglist[CAPROW];
__device__ float  g_zg[(size_t)D_ * CAPROW];       // gathered flagged z columns
__device__ float  g_rpv[NSLICE][CAPROW];
__device__ int    g_rpi[NSLICE][CAPROW];
__device__ double g_loss;

__device__ __forceinline__ uint32_t smem_u32(const void* p) {
    uint32_t a;
    asm("{ .reg .u64 t; cvta.to.shared.u64 t, %1; cvt.u32.u64 %0, t; }" : "=r"(a) : "l"(p));
    return a;
}

#define MMA_TF32(d, a, bb)                                                     \
    asm volatile("mma.sync.aligned.m16n8k8.row.col.f32.tf32.tf32.f32 "         \
        "{%0,%1,%2,%3}, {%4,%5,%6,%7}, {%8,%9}, {%0,%1,%2,%3};"                \
        : "+f"((d)[0]), "+f"((d)[1]), "+f"((d)[2]), "+f"((d)[3])               \
        : "r"((a)[0]), "r"((a)[1]), "r"((a)[2]), "r"((a)[3]),                  \
          "r"((bb)[0]), "r"((bb)[1]))

// ---- small kernels ----
__global__ void init_kernel() { g_loss = 0.0; g_flagcnt = 0; }

__global__ void finalize_kernel(float* __restrict__ out) {
    out[ZQ_ELEMS + IND_ELEMS] = (float)(2.25 * g_loss / ((double)B_ * D_ * L_));
}

// =====================================================================
// Screen: tf32 mma.sync GEMM (codes x l) with fused per-column top-2.
// CTA: M=128 codes (loop 8 supertiles), N=128 l-cols, K=512 (chunks of 32).
// 8 warps as 2(M) x 4(N); warp tile m64 x n32 = 4x4 mma tiles.
// smem layout (floats):
//   As: 2 stages x [128 rows][36]   (k-chunk 32 + pad 4)
//   Bs: 2 stages x [32 k][136]      (128 cols + pad 8)
//   warp slots + running top-2 arrays after that.
// =====================================================================
#define SAS_ST (128 * 36)
#define SBS_ST (32 * 136)
#define SW_OFF (2 * SAS_ST + 2 * SBS_ST)
#define SMEM_SCREEN ((SW_OFF + 6 * 128 + 3 * 128) * 4)

__device__ __forceinline__ void screen_issue(
    const float* __restrict__ W, const float* __restrict__ zb,
    uint32_t sAs, uint32_t sBs, int nsup, int kc, int st, int tid, int lb)
{
    const int kb = kc * 32;
    #pragma unroll
    for (int i = 0; i < 4; ++i) {
        int v = tid + i * 256;
        int row = v >> 3, cq = v & 7;
        uint32_t dst = sAs + (uint32_t)((st * SAS_ST + row * 36 + cq * 4) * 4);
        const float* src = W + (size_t)(nsup * 128 + row) * D_ + kb + cq * 4;
        asm volatile("cp.async.cg.shared.global [%0], [%1], 16;"
                     :: "r"(dst), "l"(src) : "memory");
    }
    #pragma unroll
    for (int i = 0; i < 4; ++i) {
        int v = tid + i * 256;
        int kr = v >> 5, cq = v & 31;
        uint32_t dst = sBs + (uint32_t)((st * SBS_ST + kr * 136 + cq * 4) * 4);
        const float* src = zb + (size_t)(kb + kr) * L_ + lb + cq * 4;
        uint32_t ssz = (lb + cq * 4 < L_) ? 16u : 0u;   // zero-fill OOB cols
        asm volatile("cp.async.cg.shared.global [%0], [%1], 16, %2;"
                     :: "r"(dst), "l"(src), "r"(ssz) : "memory");
    }
    asm volatile("cp.async.commit_group;" ::: "memory");
}

__global__ void __launch_bounds__(256, 2)
screen_kernel(const float* __restrict__ z, const float* __restrict__ W)
{
    extern __shared__ float sm[];
    float* wv1 = sm + SW_OFF;            // [2][128]
    float* wv2 = wv1 + 256;              // [2][128]
    int*   wi1 = (int*)(wv2 + 256);      // [2][128]
    float* rv1 = (float*)(wi1 + 256);    // [128]
    float* rv2 = rv1 + 128;              // [128]
    int*   ri1 = (int*)(rv2 + 128);      // [128]

    const int tid = threadIdx.x, lane = tid & 31, w = tid >> 5;
    const int mw = w >> 2, nw = w & 3;           // 2(M) x 4(N)
    const int g = lane >> 2, cth = lane & 3;
    const int b = blockIdx.y, lb = blockIdx.x * 128;
    const float* zb = z + (size_t)b * D_ * L_;

    if (tid < 128) { rv1[tid] = -3.0e38f; rv2[tid] = -3.0e38f; ri1[tid] = 0; }
    __syncthreads();

    const uint32_t sAs = smem_u32(sm);
    const uint32_t sBs = smem_u32(sm + 2 * SAS_ST);

    for (int nsup = 0; nsup < 8; ++nsup) {
        float c[4][4][4];
        #pragma unroll
        for (int mt = 0; mt < 4; ++mt)
            #pragma unroll
            for (int nt = 0; nt < 4; ++nt)
                #pragma unroll
                for (int r = 0; r < 4; ++r) c[mt][nt][r] = 0.0f;

        screen_issue(W, zb, sAs, sBs, nsup, 0, 0, tid, lb);

        for (int kc = 0; kc < 16; ++kc) {
            if (kc < 15) {
                screen_issue(W, zb, sAs, sBs, nsup, kc + 1, (kc + 1) & 1, tid, lb);
                asm volatile("cp.async.wait_group 1;" ::: "memory");
            } else {
                asm volatile("cp.async.wait_group 0;" ::: "memory");
            }
            __syncthreads();

            const float* a  = sm + (kc & 1) * SAS_ST;
            const float* bs = sm + 2 * SAS_ST + (kc & 1) * SBS_ST;

            #pragma unroll
            for (int q = 0; q < 4; ++q) {
                uint32_t af[4][4];
                #pragma unroll
                for (int mt = 0; mt < 4; ++mt) {
                    const float* ap = a + (mw * 64 + mt * 16 + g) * 36 + q * 8 + cth;
                    af[mt][0] = __float_as_uint(ap[0]);        // (g,   k)
                    af[mt][1] = __float_as_uint(ap[8 * 36]);   // (g+8, k)
                    af[mt][2] = __float_as_uint(ap[4]);        // (g,   k+4)
                    af[mt][3] = __float_as_uint(ap[8 * 36 + 4]);
                }
                uint32_t bf[4][2];
                #pragma unroll
                for (int nt = 0; nt < 4; ++nt) {
                    const float* bp = bs + (q * 8 + cth) * 136 + nw * 32 + nt * 8 + g;
                    bf[nt][0] = __float_as_uint(bp[0]);        // (k,   n)
                    bf[nt][1] = __float_as_uint(bp[4 * 136]);  // (k+4, n)
                }
                #pragma unroll
                for (int mt = 0; mt < 4; ++mt)
                    #pragma unroll
                    for (int nt = 0; nt < 4; ++nt)
                        MMA_TF32(c[mt][nt], af[mt], bf[nt]);
            }
            __syncthreads();
        }

        // ---- supertile epilogue: per-column top-2 ----
        #pragma unroll
        for (int nt = 0; nt < 4; ++nt) {
            #pragma unroll
            for (int p = 0; p < 2; ++p) {
                float v1 = -3.0e38f, v2 = -3.0e38f; int i1 = 0;
                #pragma unroll
                for (int mt = 0; mt < 4; ++mt)
                    #pragma unroll
                    for (int r = 0; r < 2; ++r) {
                        float v = c[mt][nt][r * 2 + p];
                        int code = nsup * 128 + mw * 64 + mt * 16 + r * 8 + g;
                        if (v > v1) { v2 = v1; v1 = v; i1 = code; }
                        else if (v > v2) v2 = v;
                    }
                #pragma unroll
                for (int off = 4; off < 32; off <<= 1) {
                    float ov1 = __shfl_xor_sync(~0u, v1, off);
                    float ov2 = __shfl_xor_sync(~0u, v2, off);
                    int   oi1 = __shfl_xor_sync(~0u, i1, off);
                    if (ov1 > v1) { v2 = fmaxf(v1, ov2); v1 = ov1; i1 = oi1; }
                    else          { v2 = fmaxf(v2, ov1); }
                }
                if (g == 0) {
                    int col = nw * 32 + nt * 8 + 2 * cth + p;
                    wv1[mw * 128 + col] = v1;
                    wv2[mw * 128 + col] = v2;
                    wi1[mw * 128 + col] = i1;
                }
            }
        }
        __syncthreads();
        if (tid < 128) {
            float a1 = wv1[tid], a2 = wv2[tid];       int ai = wi1[tid];
            float b1 = wv1[128 + tid], b2 = wv2[128 + tid]; int bi = wi1[128 + tid];
            float m1, m2; int mi;
            if (a1 >= b1) { m1 = a1; mi = ai; m2 = fmaxf(a2, b1); }
            else          { m1 = b1; mi = bi; m2 = fmaxf(b2, a1); }
            if (m1 > rv1[tid]) {
                rv2[tid] = fmaxf(rv1[tid], m2);
                rv1[tid] = m1; ri1[tid] = mi;
            } else {
                rv2[tid] = fmaxf(rv2[tid], m1);
            }
        }
        __syncthreads();
    }

    if (tid < 128) {
        int l = lb + tid;
        if (l < L_) {
            g_best[b * L_ + l] = ri1[tid];
            if (rv1[tid] - rv2[tid] < DELTA) {
                int s = atomicAdd(&g_flagcnt, 1);
                g_flaglist[s] = (b << 16) | l;
            }
        }
    }
}

// ---- gather flagged z columns into compact k-major matrix ----
__global__ void __launch_bounds__(256)
gather_kernel(const float* __restrict__ z)
{
    const int cnt = g_flagcnt;
    const int tid = threadIdx.x;
    for (int slot = blockIdx.x; slot < cnt; slot += gridDim.x) {
        int meta = g_flaglist[slot];
        int b = meta >> 16, l = meta & 0xFFFF;
        g_zg[(size_t)tid * CAPROW + slot] =
            z[((size_t)b * D_ + tid) * L_ + l];
        g_zg[(size_t)(tid + 256) * CAPROW + slot] =
            z[((size_t)b * D_ + tid + 256) * L_ + l];
    }
}

// ---- exact fp32 rescan of flagged columns (64 cols x 128-code slice) ----
__global__ void __launch_bounds__(128)
rescan_kernel(const float* __restrict__ W)
{
    __shared__ float Ws[32][128];
    __shared__ float Zs[32][RLT];
    __shared__ float pv[16][RLT];
    __shared__ int   pi[16][RLT];

    const int tid = threadIdx.x;
    const int tx = tid & 7, ty = tid >> 3;
    const int cnt = g_flagcnt;
    const int tiles = (cnt + RLT - 1) / RLT;

    for (int item = blockIdx.x; item < tiles * NSLICE; item += gridDim.x) {
        const int ct = item / NSLICE, ns = item % NSLICE;
        const int cb = ct * RLT, nb = ns * 128;

        float acc[8][8];
        #pragma unroll
        for (int i = 0; i < 8; ++i)
            #pragma unroll
            for (int j = 0; j < 8; ++j) acc[i][j] = 0.0f;

        for (int kc = 0; kc < 16; ++kc) {
            const int kb = kc * 32;
            __syncthreads();
            #pragma unroll
            for (int p = 0; p < 8; ++p) {      // W tile 128 codes x 32 k
                int v = tid + p * 128;
                int n = v >> 3, kq = v & 7;
                float4 wv = *reinterpret_cast<const float4*>(
                    &W[(size_t)(nb + n) * D_ + kb + kq * 4]);
                Ws[kq * 4 + 0][n] = wv.x;
                Ws[kq * 4 + 1][n] = wv.y;
                Ws[kq * 4 + 2][n] = wv.z;
                Ws[kq * 4 + 3][n] = wv.w;
            }
            #pragma unroll
            for (int p = 0; p < 4; ++p) {      // Z tile 32 k x 64 cols
                int v = tid + p * 128;
                int kr = v >> 4, cq = v & 15;
                float4 zv = *reinterpret_cast<const float4*>(
                    &g_zg[(size_t)(kb + kr) * CAPROW + cb + cq * 4]);
                *reinterpret_cast<float4*>(&Zs[kr][cq * 4]) = zv;
            }
            __syncthreads();
            #pragma unroll
            for (int k = 0; k < 32; ++k) {
                float4 wa = *reinterpret_cast<const float4*>(&Ws[k][ty * 8]);
                float4 wb = *reinterpret_cast<const float4*>(&Ws[k][ty * 8 + 4]);
                float4 za = *reinterpret_cast<const float4*>(&Zs[k][tx * 8]);
                float4 zc = *reinterpret_cast<const float4*>(&Zs[k][tx * 8 + 4]);
                float wf[8] = {wa.x, wa.y, wa.z, wa.w, wb.x, wb.y, wb.z, wb.w};
                float zf[8] = {za.x, za.y, za.z, za.w, zc.x, zc.y, zc.z, zc.w};
                #pragma unroll
                for (int i = 0; i < 8; ++i)
                    #pragma unroll
                    for (int j = 0; j < 8; ++j)
                        acc[i][j] = fmaf(wf[i], zf[j], acc[i][j]);
            }
        }
        __syncthreads();
        #pragma unroll
        for (int j = 0; j < 8; ++j) {
            float m = acc[0][j];
            int mi = nb + ty * 8;
            #pragma unroll
            for (int i = 1; i < 8; ++i) {
                float v = acc[i][j];
                if (v > m) { m = v; mi = nb + ty * 8 + i; }
            }
            pv[ty][tx * 8 + j] = m;
            pi[ty][tx * 8 + j] = mi;
        }
        __syncthreads();
        if (tid < RLT) {
            float m = pv[0][tid]; int mi = pi[0][tid];
            #pragma unroll
            for (int r = 1; r < 16; ++r) {
                float v = pv[r][tid]; int vi = pi[r][tid];
                if (v > m || (v == m && vi < mi)) { m = v; mi = vi; }
            }
            g_rpv[ns][cb + tid] = m;
            g_rpi[ns][cb + tid] = mi;
        }
        __syncthreads();
    }
}

__global__ void __launch_bounds__(256)
flagmerge_kernel()
{
    const int cnt = g_flagcnt;
    for (int s = blockIdx.x * blockDim.x + threadIdx.x; s < cnt;
         s += gridDim.x * blockDim.x) {
        float bv = g_rpv[0][s]; int bi = g_rpi[0][s];
        #pragma unroll
        for (int r = 1; r < NSLICE; ++r) {
            float v = g_rpv[r][s];
            if (v > bv) { bv = v; bi = g_rpi[r][s]; }
        }
        int meta = g_flaglist[s];
        g_best[(meta >> 16) * L_ + (meta & 0xFFFF)] = bi;
    }
}

// ---- output: ind + z_q gather + loss ----
__global__ void __launch_bounds__(256)
output_kernel(const float* __restrict__ z, const float* __restrict__ W,
              float* __restrict__ out)
{
    __shared__ int besti[256];
    __shared__ double red[256];
    const int tid = threadIdx.x;
    const int b = blockIdx.x / 12, lt = blockIdx.x % 12;
    const int lbase = lt * 256;
    const int valid = (L_ - lbase < 256) ? (L_ - lbase) : 256;

    if (tid < valid) {
        int bi = g_best[b * L_ + lbase + tid];
        besti[tid] = bi;
        out[ZQ_ELEMS + (size_t)b * L_ + lbase + tid] = (float)bi;
    }
    __syncthreads();

    const float* zb = z + (size_t)b * D_ * L_;
    double lsum = 0.0;
    #pragma unroll 4
    for (int p = 0; p < (D_ * 256) / 256; ++p) {
        int idx = p * 256 + tid;
        int col = idx & 255;
        int d = idx >> 8;
        if (col < valid) {
            int l = lbase + col;
            float wv = W[(size_t)besti[col] * D_ + d];
            float zv = zb[(size_t)d * L_ + l];
            out[((size_t)b * D_ + d) * L_ + l] = wv;
            float df = wv - zv;
            lsum += (double)df * (double)df;
        }
    }
    red[tid] = lsum;
    __syncthreads();
    #pragma unroll
    for (int s = 128; s > 0; s >>= 1) {
        if (tid < s) red[tid] += red[tid + s];
        __syncthreads();
    }
    if (tid == 0) atomicAdd(&g_loss, red[0]);
}

extern "C" void kernel_launch(void* const* d_in, const int* in_sizes, int n_in,
                              void* d_out, int out_size) {
    const float* z = (const float*)d_in[0];
    const float* W = (const float*)d_in[1];
    if (n_in >= 2 && in_sizes[0] == NE_ * D_) {   // defensive order check
        z = (const float*)d_in[1];
        W = (const float*)d_in[0];
    }
    float* out = (float*)d_out;

    cudaFuncSetAttribute(screen_kernel,
                         cudaFuncAttributeMaxDynamicSharedMemorySize, SMEM_SCREEN);

    init_kernel<<<1, 1>>>();
    {
        dim3 grd((L_ + 127) / 128, B_);
        screen_kernel<<<grd, 256, SMEM_SCREEN>>>(z, W);
    }
    gather_kernel<<<256, 256>>>(z);
    rescan_kernel<<<512, 128>>>(W);
    flagmerge_kernel<<<64, 256>>>();
    output_kernel<<<B_ * 12, 256>>>(z, W, out);
    finalize_kernel<<<1, 1>>>(out);
}

// round 6
// speedup vs baseline: 2.9789x; 1.0494x over previous
#include <cuda_runtime.h>
#include <cstdint>

#define B_    16
#define D_    512
#define L_    3000
#define NE_   1024
#define ZQ_ELEMS  ((size_t)B_ * D_ * L_)
#define IND_ELEMS ((size_t)B_ * L_)

#define DELTA   0.5f          // bf16 screen margin (~10 sigma)
#define CAPROW  49152
#define NSLICE  8
#define RLT     64

// ---- device scratch (no allocation allowed anywhere) ----
__device__ __align__(16) unsigned short g_zb[(size_t)B_ * D_ * L_];  // z bf16
__device__ __align__(16) unsigned short g_wb[(size_t)NE_ * D_];      // W bf16
__device__ int    g_best[B_ * L_];
__device__ int    g_flagcnt;
__device__ int    g_flaglist[CAPROW];
__device__ float  g_zg[(size_t)D_ * CAPROW];
__device__ float  g_rpv[NSLICE][CAPROW];
__device__ int    g_rpi[NSLICE][CAPROW];
__device__ double g_loss;

__device__ __forceinline__ uint32_t smem_u32(const void* p) {
    uint32_t a;
    asm("{ .reg .u64 t; cvta.to.shared.u64 t, %1; cvt.u32.u64 %0, t; }" : "=r"(a) : "l"(p));
    return a;
}
__device__ __forceinline__ unsigned short f2bf(float f) {   // RN-even
    uint32_t u = __float_as_uint(f);
    return (unsigned short)((u + 0x7FFFu + ((u >> 16) & 1u)) >> 16);
}

#define MMA_BF16(d, a, bb)                                                     \
    asm volatile("mma.sync.aligned.m16n8k16.row.col.f32.bf16.bf16.f32 "        \
        "{%0,%1,%2,%3}, {%4,%5,%6,%7}, {%8,%9}, {%0,%1,%2,%3};"                \
        : "+f"((d)[0]), "+f"((d)[1]), "+f"((d)[2]), "+f"((d)[3])               \
        : "r"((a)[0]), "r"((a)[1]), "r"((a)[2]), "r"((a)[3]),                  \
          "r"((bb)[0]), "r"((bb)[1]))

#define LDMX4(r, addr)                                                         \
    asm volatile("ldmatrix.sync.aligned.m8n8.x4.shared.b16 {%0,%1,%2,%3}, [%4];" \
        : "=r"((r)[0]), "=r"((r)[1]), "=r"((r)[2]), "=r"((r)[3]) : "r"(addr))

#define LDMX2T(r, addr)                                                        \
    asm volatile("ldmatrix.sync.aligned.m8n8.x2.trans.shared.b16 {%0,%1}, [%2];" \
        : "=r"((r)[0]), "=r"((r)[1]) : "r"(addr))

// ---- small kernels ----
__global__ void init_kernel() { g_loss = 0.0; g_flagcnt = 0; }

__global__ void finalize_kernel(float* __restrict__ out) {
    out[ZQ_ELEMS + IND_ELEMS] = (float)(2.25 * g_loss / ((double)B_ * D_ * L_));
}

__global__ void convert_w_kernel(const float* __restrict__ W) {
    int i4 = blockIdx.x * blockDim.x + threadIdx.x;   // 131072 threads
    size_t base = (size_t)i4 * 4;
    float4 v = *reinterpret_cast<const float4*>(W + base);
    uint2 o;
    o.x = (uint32_t)f2bf(v.x) | ((uint32_t)f2bf(v.y) << 16);
    o.y = (uint32_t)f2bf(v.z) | ((uint32_t)f2bf(v.w) << 16);
    *reinterpret_cast<uint2*>(g_wb + base) = o;
}

__global__ void convert_z_kernel(const float* __restrict__ z) {
    int i4 = blockIdx.x * blockDim.x + threadIdx.x;   // 6144000 threads
    if (i4 >= (int)(ZQ_ELEMS / 4)) return;
    size_t base = (size_t)i4 * 4;
    float4 v = *reinterpret_cast<const float4*>(z + base);
    uint2 o;
    o.x = (uint32_t)f2bf(v.x) | ((uint32_t)f2bf(v.y) << 16);
    o.y = (uint32_t)f2bf(v.z) | ((uint32_t)f2bf(v.w) << 16);
    *reinterpret_cast<uint2*>(g_zb + base) = o;
}

// =====================================================================
// Screen: bf16 mma.sync m16n8k16, fused per-column top-2 + margin flag.
// CTA 256 thr = 8 warps (2M x 4N), CTA tile 128 codes x 128 cols,
// looped over 8 code-supertiles; K chunks of 32 double-buffered cp.async.
// A smem row stride 80B, B smem row stride 272B (conflict-free ldmatrix).
// =====================================================================
#define AST   10240            // 128 * 80
#define BST   8704             // 32 * 272
#define BOFF  20480            // 2 * AST
#define EOFF  37888            // BOFF + 2 * BST
#define SMEM_SCREEN (EOFF + 4608)

__device__ __forceinline__ void screen_issue(
    const unsigned short* __restrict__ wb, const unsigned short* __restrict__ zrow,
    uint32_t sbase, int nsup, int kc, int st, int tid, int lb)
{
    const int kb = kc * 32;
    #pragma unroll
    for (int i = 0; i < 2; ++i) {            // A: 128 rows x 4 chunks
        int v = tid + i * 256;
        int row = v >> 2, ch = v & 3;
        uint32_t dst = sbase + st * AST + row * 80 + ch * 16;
        const unsigned short* src = wb + (size_t)(nsup * 128 + row) * D_ + kb + ch * 8;
        asm volatile("cp.async.cg.shared.global [%0], [%1], 16;"
                     :: "r"(dst), "l"(src) : "memory");
    }
    #pragma unroll
    for (int i = 0; i < 2; ++i) {            // B: 32 k-rows x 16 chunks
        int v = tid + i * 256;
        int kr = v >> 4, ch = v & 15;
        uint32_t dst = sbase + BOFF + st * BST + kr * 272 + ch * 16;
        const unsigned short* src = zrow + (size_t)(kb + kr) * L_ + lb + ch * 8;
        uint32_t ssz = (lb + ch * 8 < L_) ? 16u : 0u;
        asm volatile("cp.async.cg.shared.global [%0], [%1], 16, %2;"
                     :: "r"(dst), "l"(src), "r"(ssz) : "memory");
    }
    asm volatile("cp.async.commit_group;" ::: "memory");
}

__global__ void __launch_bounds__(256, 2)
screen_kernel()
{
    extern __shared__ char smc[];
    const uint32_t sbase = smem_u32(smc);
    float* ep  = (float*)(smc + EOFF);
    float* wv1 = ep;                 // [2][128]
    float* wv2 = ep + 256;
    int*   wi1 = (int*)(ep + 512);
    float* rv1 = ep + 768;
    float* rv2 = ep + 896;
    int*   ri1 = (int*)(ep + 1024);

    const int tid = threadIdx.x, lane = tid & 31, w = tid >> 5;
    const int mw = w >> 2, nw = w & 3;
    const int g = lane >> 2, cth = lane & 3;
    const int b = blockIdx.y, lb = blockIdx.x * 128;
    const unsigned short* zrow = g_zb + (size_t)b * D_ * L_;

    if (tid < 128) { rv1[tid] = -3.0e38f; rv2[tid] = -3.0e38f; ri1[tid] = 0; }
    __syncthreads();

    // lane-constant ldmatrix offsets
    const uint32_t offA = (uint32_t)((lane & 15) * 80 + (lane >> 4) * 16);
    const uint32_t offB = (uint32_t)((lane & 15) * 272);

    for (int nsup = 0; nsup < 8; ++nsup) {
        float c[4][4][4];
        #pragma unroll
        for (int mt = 0; mt < 4; ++mt)
            #pragma unroll
            for (int nt = 0; nt < 4; ++nt)
                #pragma unroll
                for (int r = 0; r < 4; ++r) c[mt][nt][r] = 0.0f;

        screen_issue(g_wb, zrow, sbase, nsup, 0, 0, tid, lb);

        for (int kc = 0; kc < 16; ++kc) {
            if (kc < 15) {
                screen_issue(g_wb, zrow, sbase, nsup, kc + 1, (kc + 1) & 1, tid, lb);
                asm volatile("cp.async.wait_group 1;" ::: "memory");
            } else {
                asm volatile("cp.async.wait_group 0;" ::: "memory");
            }
            __syncthreads();

            const int st = kc & 1;
            const uint32_t aB = sbase + st * AST;
            const uint32_t bB = sbase + BOFF + st * BST;

            #pragma unroll
            for (int q = 0; q < 2; ++q) {
                uint32_t af[4][4], bf[4][2];
                #pragma unroll
                for (int mt = 0; mt < 4; ++mt)
                    LDMX4(af[mt], aB + (uint32_t)((mw * 64 + mt * 16) * 80 + q * 32) + offA);
                #pragma unroll
                for (int nt = 0; nt < 4; ++nt)
                    LDMX2T(bf[nt], bB + (uint32_t)(q * 16 * 272 + nw * 64 + nt * 16) + offB);
                #pragma unroll
                for (int mt = 0; mt < 4; ++mt)
                    #pragma unroll
                    for (int nt = 0; nt < 4; ++nt)
                        MMA_BF16(c[mt][nt], af[mt], bf[nt]);
            }
            __syncthreads();
        }

        // ---- supertile epilogue: per-column top-2 ----
        #pragma unroll
        for (int nt = 0; nt < 4; ++nt) {
            #pragma unroll
            for (int p = 0; p < 2; ++p) {
                float v1 = -3.0e38f, v2 = -3.0e38f; int i1 = 0;
                #pragma unroll
                for (int mt = 0; mt < 4; ++mt)
                    #pragma unroll
                    for (int r = 0; r < 2; ++r) {
                        float v = c[mt][nt][r * 2 + p];
                        int code = nsup * 128 + mw * 64 + mt * 16 + r * 8 + g;
                        if (v > v1) { v2 = v1; v1 = v; i1 = code; }
                        else if (v > v2) v2 = v;
                    }
                #pragma unroll
                for (int off = 4; off < 32; off <<= 1) {
                    float ov1 = __shfl_xor_sync(~0u, v1, off);
                    float ov2 = __shfl_xor_sync(~0u, v2, off);
                    int   oi1 = __shfl_xor_sync(~0u, i1, off);
                    if (ov1 > v1) { v2 = fmaxf(v1, ov2); v1 = ov1; i1 = oi1; }
                    else          { v2 = fmaxf(v2, ov1); }
                }
                if (g == 0) {
                    int col = nw * 32 + nt * 8 + 2 * cth + p;
                    wv1[mw * 128 + col] = v1;
                    wv2[mw * 128 + col] = v2;
                    wi1[mw * 128 + col] = i1;
                }
            }
        }
        __syncthreads();
        if (tid < 128) {
            float a1 = wv1[tid], a2 = wv2[tid];             int ai = wi1[tid];
            float b1 = wv1[128 + tid], b2 = wv2[128 + tid]; int bi = wi1[128 + tid];
            float m1, m2; int mi;
            if (a1 >= b1) { m1 = a1; mi = ai; m2 = fmaxf(a2, b1); }
            else          { m1 = b1; mi = bi; m2 = fmaxf(b2, a1); }
            if (m1 > rv1[tid]) {
                rv2[tid] = fmaxf(rv1[tid], m2);
                rv1[tid] = m1; ri1[tid] = mi;
            } else {
                rv2[tid] = fmaxf(rv2[tid], m1);
            }
        }
        __syncthreads();
    }

    if (tid < 128) {
        int l = lb + tid;
        if (l < L_) {
            g_best[b * L_ + l] = ri1[tid];
            if (rv1[tid] - rv2[tid] < DELTA) {
                int s = atomicAdd(&g_flagcnt, 1);
                g_flaglist[s] = (b << 16) | l;
            }
        }
    }
}

// ---- gather flagged z columns into compact k-major matrix ----
__global__ void __launch_bounds__(256)
gather_kernel(const float* __restrict__ z)
{
    const int cnt = g_flagcnt;
    const int tid = threadIdx.x;
    for (int slot = blockIdx.x; slot < cnt; slot += gridDim.x) {
        int meta = g_flaglist[slot];
        int b = meta >> 16, l = meta & 0xFFFF;
        g_zg[(size_t)tid * CAPROW + slot] = z[((size_t)b * D_ + tid) * L_ + l];
        g_zg[(size_t)(tid + 256) * CAPROW + slot] =
            z[((size_t)b * D_ + tid + 256) * L_ + l];
    }
}

// ---- exact fp32 rescan: 256 thr, item = 64 cols x 128-code slice ----
__global__ void __launch_bounds__(256)
rescan_kernel(const float* __restrict__ W)
{
    __shared__ float Ws[32][128];
    __shared__ float Zs[32][RLT];
    __shared__ float pv[32][RLT];
    __shared__ int   pi[32][RLT];

    const int tid = threadIdx.x;
    const int tx = tid & 7, ty = tid >> 3;     // 8 col-groups x 32 code-groups
    const int cnt = g_flagcnt;
    const int tiles = (cnt + RLT - 1) / RLT;

    for (int item = blockIdx.x; item < tiles * NSLICE; item += gridDim.x) {
        const int ct = item / NSLICE, ns = item % NSLICE;
        const int cb = ct * RLT, nb = ns * 128;

        float acc[4][8];
        #pragma unroll
        for (int i = 0; i < 4; ++i)
            #pragma unroll
            for (int j = 0; j < 8; ++j) acc[i][j] = 0.0f;

        for (int kc = 0; kc < 16; ++kc) {
            const int kb = kc * 32;
            __syncthreads();
            #pragma unroll
            for (int p = 0; p < 4; ++p) {          // W tile 128 codes x 32 k
                int v = tid + p * 256;
                int n = v >> 3, kq = v & 7;
                float4 wv = *reinterpret_cast<const float4*>(
                    &W[(size_t)(nb + n) * D_ + kb + kq * 4]);
                Ws[kq * 4 + 0][n] = wv.x;
                Ws[kq * 4 + 1][n] = wv.y;
                Ws[kq * 4 + 2][n] = wv.z;
                Ws[kq * 4 + 3][n] = wv.w;
            }
            #pragma unroll
            for (int p = 0; p < 2; ++p) {          // Z tile 32 k x 64 cols
                int v = tid + p * 256;
                int kr = v >> 4, cq = v & 15;
                float4 zv = *reinterpret_cast<const float4*>(
                    &g_zg[(size_t)(kb + kr) * CAPROW + cb + cq * 4]);
                *reinterpret_cast<float4*>(&Zs[kr][cq * 4]) = zv;
            }
            __syncthreads();
            #pragma unroll
            for (int k = 0; k < 32; ++k) {
                float4 wa = *reinterpret_cast<const float4*>(&Ws[k][ty * 4]);
                float4 za = *reinterpret_cast<const float4*>(&Zs[k][tx * 8]);
                float4 zc = *reinterpret_cast<const float4*>(&Zs[k][tx * 8 + 4]);
                float wf[4] = {wa.x, wa.y, wa.z, wa.w};
                float zf[8] = {za.x, za.y, za.z, za.w, zc.x, zc.y, zc.z, zc.w};
                #pragma unroll
                for (int i = 0; i < 4; ++i)
                    #pragma unroll
                    for (int j = 0; j < 8; ++j)
                        acc[i][j] = fmaf(wf[i], zf[j], acc[i][j]);
            }
        }
        __syncthreads();
        #pragma unroll
        for (int j = 0; j < 8; ++j) {
            float m = acc[0][j];
            int mi = nb + ty * 4;
            #pragma unroll
            for (int i = 1; i < 4; ++i) {
                float v = acc[i][j];
                if (v > m) { m = v; mi = nb + ty * 4 + i; }
            }
            pv[ty][tx * 8 + j] = m;
            pi[ty][tx * 8 + j] = mi;
        }
        __syncthreads();
        if (tid < RLT) {
            float m = pv[0][tid]; int mi = pi[0][tid];
            #pragma unroll
            for (int r = 1; r < 32; ++r) {
                float v = pv[r][tid]; int vi = pi[r][tid];
                if (v > m || (v == m && vi < mi)) { m = v; mi = vi; }
            }
            g_rpv[ns][cb + tid] = m;
            g_rpi[ns][cb + tid] = mi;
        }
        __syncthreads();
    }
}

__global__ void __launch_bounds__(256)
flagmerge_kernel()
{
    const int cnt = g_flagcnt;
    for (int s = blockIdx.x * blockDim.x + threadIdx.x; s < cnt;
         s += gridDim.x * blockDim.x) {
        float bv = g_rpv[0][s]; int bi = g_rpi[0][s];
        #pragma unroll
        for (int r = 1; r < NSLICE; ++r) {
            float v = g_rpv[r][s];
            if (v > bv) { bv = v; bi = g_rpi[r][s]; }
        }
        int meta = g_flaglist[s];
        g_best[(meta >> 16) * L_ + (meta & 0xFFFF)] = bi;
    }
}

// ---- output: ind + z_q gather + loss ----
__global__ void __launch_bounds__(256)
output_kernel(const float* __restrict__ z, const float* __restrict__ W,
              float* __restrict__ out)
{
    __shared__ int besti[256];
    __shared__ double red[256];
    const int tid = threadIdx.x;
    const int b = blockIdx.x / 12, lt = blockIdx.x % 12;
    const int lbase = lt * 256;
    const int valid = (L_ - lbase < 256) ? (L_ - lbase) : 256;

    if (tid < valid) {
        int bi = g_best[b * L_ + lbase + tid];
        besti[tid] = bi;
        out[ZQ_ELEMS + (size_t)b * L_ + lbase + tid] = (float)bi;
    }
    __syncthreads();

    const float* zb = z + (size_t)b * D_ * L_;
    double lsum = 0.0;
    #pragma unroll 4
    for (int p = 0; p < D_; ++p) {
        int col = tid;
        int d = p;
        if (col < valid) {
            int l = lbase + col;
            float wv = W[(size_t)besti[col] * D_ + d];
            float zv = zb[(size_t)d * L_ + l];
            out[((size_t)b * D_ + d) * L_ + l] = wv;
            float df = wv - zv;
            lsum += (double)df * (double)df;
        }
    }
    red[tid] = lsum;
    __syncthreads();
    #pragma unroll
    for (int s = 128; s > 0; s >>= 1) {
        if (tid < s) red[tid] += red[tid + s];
        __syncthreads();
    }
    if (tid == 0) atomicAdd(&g_loss, red[0]);
}

extern "C" void kernel_launch(void* const* d_in, const int* in_sizes, int n_in,
                              void* d_out, int out_size) {
    const float* z = (const float*)d_in[0];
    const float* W = (const float*)d_in[1];
    if (n_in >= 2 && in_sizes[0] == NE_ * D_) {
        z = (const float*)d_in[1];
        W = (const float*)d_in[0];
    }
    float* out = (float*)d_out;

    cudaFuncSetAttribute(screen_kernel,
                         cudaFuncAttributeMaxDynamicSharedMemorySize, SMEM_SCREEN);

    init_kernel<<<1, 1>>>();
    convert_w_kernel<<<(NE_ * D_ / 4 + 255) / 256, 256>>>(W);
    convert_z_kernel<<<((int)(ZQ_ELEMS / 4) + 255) / 256, 256>>>(z);
    {
        dim3 grd((L_ + 127) / 128, B_);
        screen_kernel<<<grd, 256, SMEM_SCREEN>>>();
    }
    gather_kernel<<<256, 256>>>(z);
    rescan_kernel<<<512, 256>>>(W);
    flagmerge_kernel<<<64, 256>>>();
    output_kernel<<<B_ * 12, 256>>>(z, W, out);
    finalize_kernel<<<1, 1>>>(out);
}

// round 7
// speedup vs baseline: 3.4374x; 1.1539x over previous
#include <cuda_runtime.h>
#include <cstdint>

#define B_    16
#define D_    512
#define L_    3000
#define NE_   1024
#define ZQ_ELEMS  ((size_t)B_ * D_ * L_)
#define IND_ELEMS ((size_t)B_ * L_)

#define DELTA   0.25f         // bf16 screen margin (~11 sigma)
#define CAPROW  49152
#define NSLICE  8
#define RLT     64

// ---- device scratch (no allocation allowed anywhere) ----
__device__ __align__(16) unsigned short g_zb[(size_t)B_ * D_ * L_];
__device__ __align__(16) unsigned short g_wb[(size_t)NE_ * D_];
__device__ int    g_best[B_ * L_];
__device__ int    g_flagcnt;
__device__ int    g_flaglist[CAPROW];
__device__ float  g_zg[(size_t)D_ * CAPROW];
__device__ float  g_rpv[NSLICE][CAPROW];
__device__ int    g_rpi[NSLICE][CAPROW];
__device__ double g_loss;

__device__ __forceinline__ uint32_t smem_u32(const void* p) {
    uint32_t a;
    asm("{ .reg .u64 t; cvta.to.shared.u64 t, %1; cvt.u32.u64 %0, t; }" : "=r"(a) : "l"(p));
    return a;
}
__device__ __forceinline__ unsigned short f2bf(float f) {   // RN-even
    uint32_t u = __float_as_uint(f);
    return (unsigned short)((u + 0x7FFFu + ((u >> 16) & 1u)) >> 16);
}

#define MMA_BF16(d, a, bb)                                                     \
    asm volatile("mma.sync.aligned.m16n8k16.row.col.f32.bf16.bf16.f32 "        \
        "{%0,%1,%2,%3}, {%4,%5,%6,%7}, {%8,%9}, {%0,%1,%2,%3};"                \
        : "+f"((d)[0]), "+f"((d)[1]), "+f"((d)[2]), "+f"((d)[3])               \
        : "r"((a)[0]), "r"((a)[1]), "r"((a)[2]), "r"((a)[3]),                  \
          "r"((bb)[0]), "r"((bb)[1]))

#define LDMX4(r, addr)                                                         \
    asm volatile("ldmatrix.sync.aligned.m8n8.x4.shared.b16 {%0,%1,%2,%3}, [%4];" \
        : "=r"((r)[0]), "=r"((r)[1]), "=r"((r)[2]), "=r"((r)[3]) : "r"(addr))

#define LDMX2T(r, addr)                                                        \
    asm volatile("ldmatrix.sync.aligned.m8n8.x2.trans.shared.b16 {%0,%1}, [%2];" \
        : "=r"((r)[0]), "=r"((r)[1]) : "r"(addr))

// ---- small kernels ----
__global__ void init_kernel() { g_loss = 0.0; g_flagcnt = 0; }

__global__ void finalize_kernel(float* __restrict__ out) {
    out[ZQ_ELEMS + IND_ELEMS] = (float)(2.25 * g_loss / ((double)B_ * D_ * L_));
}

__global__ void convert_w_kernel(const float* __restrict__ W) {
    int i4 = blockIdx.x * blockDim.x + threadIdx.x;
    size_t base = (size_t)i4 * 4;
    float4 v = *reinterpret_cast<const float4*>(W + base);
    uint2 o;
    o.x = (uint32_t)f2bf(v.x) | ((uint32_t)f2bf(v.y) << 16);
    o.y = (uint32_t)f2bf(v.z) | ((uint32_t)f2bf(v.w) << 16);
    *reinterpret_cast<uint2*>(g_wb + base) = o;
}

__global__ void convert_z_kernel(const float* __restrict__ z) {
    int i4 = blockIdx.x * blockDim.x + threadIdx.x;
    if (i4 >= (int)(ZQ_ELEMS / 4)) return;
    size_t base = (size_t)i4 * 4;
    float4 v = *reinterpret_cast<const float4*>(z + base);
    uint2 o;
    o.x = (uint32_t)f2bf(v.x) | ((uint32_t)f2bf(v.y) << 16);
    o.y = (uint32_t)f2bf(v.z) | ((uint32_t)f2bf(v.w) << 16);
    *reinterpret_cast<uint2*>(g_zb + base) = o;
}

// =====================================================================
// Screen: bf16 mma m16n8k16; CTA 128 codes x 128 cols, 8 supertiles;
// K-chunk 64, 3-stage cp.async ring, ONE __syncthreads per k-iter.
// A rows 144B stride, B rows 272B stride (conflict-free ldmatrix).
// =====================================================================
#define AST   18432            // 128 * 144
#define BST   17408            // 64 * 272
#define BOFF  (3 * AST)        // 55296
#define EOFF  (3 * (AST + BST))// 107520
#define SMEM_SCREEN (EOFF + 4608)

__device__ __forceinline__ void screen_issue(
    const unsigned short* __restrict__ zrow,
    uint32_t sbase, int t, int tid, int lb)
{
    const int nsup = t >> 3;
    const int kb = (t & 7) * 64;
    const int st = t % 3;
    #pragma unroll
    for (int i = 0; i < 4; ++i) {            // A: 128 rows x 8 chunks(16B)
        int v = tid + i * 256;
        int row = v >> 3, ch = v & 7;
        uint32_t dst = sbase + st * AST + row * 144 + ch * 16;
        const unsigned short* src = g_wb + (size_t)(nsup * 128 + row) * D_ + kb + ch * 8;
        asm volatile("cp.async.cg.shared.global [%0], [%1], 16;"
                     :: "r"(dst), "l"(src) : "memory");
    }
    #pragma unroll
    for (int i = 0; i < 4; ++i) {            // B: 64 k-rows x 16 chunks
        int v = tid + i * 256;
        int kr = v >> 4, ch = v & 15;
        uint32_t dst = sbase + BOFF + st * BST + kr * 272 + ch * 16;
        const unsigned short* src = zrow + (size_t)(kb + kr) * L_ + lb + ch * 8;
        uint32_t ssz = (lb + ch * 8 < L_) ? 16u : 0u;
        asm volatile("cp.async.cg.shared.global [%0], [%1], 16, %2;"
                     :: "r"(dst), "l"(src), "r"(ssz) : "memory");
    }
    asm volatile("cp.async.commit_group;" ::: "memory");
}

__global__ void __launch_bounds__(256, 2)
screen_kernel()
{
    extern __shared__ char smc[];
    const uint32_t sbase = smem_u32(smc);
    float* ep  = (float*)(smc + EOFF);
    float* wv1 = ep;                 // [2][128]
    float* wv2 = ep + 256;
    int*   wi1 = (int*)(ep + 512);
    float* rv1 = ep + 768;
    float* rv2 = ep + 896;
    int*   ri1 = (int*)(ep + 1024);

    const int tid = threadIdx.x, lane = tid & 31, w = tid >> 5;
    const int mw = w >> 2, nw = w & 3;
    const int g = lane >> 2, cth = lane & 3;
    const int b = blockIdx.y, lb = blockIdx.x * 128;
    const unsigned short* zrow = g_zb + (size_t)b * D_ * L_;

    if (tid < 128) { rv1[tid] = -3.0e38f; rv2[tid] = -3.0e38f; ri1[tid] = 0; }

    const uint32_t offA = (uint32_t)((lane & 15) * 144 + (lane >> 4) * 16);
    const uint32_t offB = (uint32_t)((lane & 15) * 272);

    float c[4][4][4];

    screen_issue(zrow, sbase, 0, tid, lb);
    screen_issue(zrow, sbase, 1, tid, lb);

    for (int t = 0; t < 64; ++t) {
        const int kc = t & 7, nsup = t >> 3, st = t % 3;

        if (t < 62) asm volatile("cp.async.wait_group 1;" ::: "memory");
        else        asm volatile("cp.async.wait_group 0;" ::: "memory");
        __syncthreads();
        if (t < 62) screen_issue(zrow, sbase, t + 2, tid, lb);

        if (kc == 0) {
            #pragma unroll
            for (int mt = 0; mt < 4; ++mt)
                #pragma unroll
                for (int nt = 0; nt < 4; ++nt)
                    #pragma unroll
                    for (int r = 0; r < 4; ++r) c[mt][nt][r] = 0.0f;
        }

        const uint32_t aB = sbase + st * AST;
        const uint32_t bB = sbase + BOFF + st * BST;
        #pragma unroll
        for (int q = 0; q < 4; ++q) {
            uint32_t af[4][4], bf[4][2];
            #pragma unroll
            for (int mt = 0; mt < 4; ++mt)
                LDMX4(af[mt], aB + (uint32_t)((mw * 64 + mt * 16) * 144 + q * 32) + offA);
            #pragma unroll
            for (int nt = 0; nt < 4; ++nt)
                LDMX2T(bf[nt], bB + (uint32_t)(q * 16 * 272 + nw * 64 + nt * 16) + offB);
            #pragma unroll
            for (int mt = 0; mt < 4; ++mt)
                #pragma unroll
                for (int nt = 0; nt < 4; ++nt)
                    MMA_BF16(c[mt][nt], af[mt], bf[nt]);
        }

        if (kc == 7) {
            // ---- supertile epilogue: per-column top-2 ----
            #pragma unroll
            for (int nt = 0; nt < 4; ++nt) {
                #pragma unroll
                for (int p = 0; p < 2; ++p) {
                    float v1 = -3.0e38f, v2 = -3.0e38f; int i1 = 0;
                    #pragma unroll
                    for (int mt = 0; mt < 4; ++mt)
                        #pragma unroll
                        for (int r = 0; r < 2; ++r) {
                            float v = c[mt][nt][r * 2 + p];
                            int code = nsup * 128 + mw * 64 + mt * 16 + r * 8 + g;
                            if (v > v1) { v2 = v1; v1 = v; i1 = code; }
                            else if (v > v2) v2 = v;
                        }
                    #pragma unroll
                    for (int off = 4; off < 32; off <<= 1) {
                        float ov1 = __shfl_xor_sync(~0u, v1, off);
                        float ov2 = __shfl_xor_sync(~0u, v2, off);
                        int   oi1 = __shfl_xor_sync(~0u, i1, off);
                        if (ov1 > v1) { v2 = fmaxf(v1, ov2); v1 = ov1; i1 = oi1; }
                        else          { v2 = fmaxf(v2, ov1); }
                    }
                    if (g == 0) {
                        int col = nw * 32 + nt * 8 + 2 * cth + p;
                        wv1[mw * 128 + col] = v1;
                        wv2[mw * 128 + col] = v2;
                        wi1[mw * 128 + col] = i1;
                    }
                }
            }
            __syncthreads();
            if (tid < 128) {
                float a1 = wv1[tid], a2 = wv2[tid];             int ai = wi1[tid];
                float b1 = wv1[128 + tid], b2 = wv2[128 + tid]; int bi = wi1[128 + tid];
                float m1, m2; int mi;
                if (a1 >= b1) { m1 = a1; mi = ai; m2 = fmaxf(a2, b1); }
                else          { m1 = b1; mi = bi; m2 = fmaxf(b2, a1); }
                if (m1 > rv1[tid]) {
                    rv2[tid] = fmaxf(rv1[tid], m2);
                    rv1[tid] = m1; ri1[tid] = mi;
                } else {
                    rv2[tid] = fmaxf(rv2[tid], m1);
                }
            }
            __syncthreads();
        }
    }

    if (tid < 128) {
        int l = lb + tid;
        if (l < L_) {
            g_best[b * L_ + l] = ri1[tid];
            if (rv1[tid] - rv2[tid] < DELTA) {
                int s = atomicAdd(&g_flagcnt, 1);
                g_flaglist[s] = (b << 16) | l;
            }
        }
    }
}

// ---- gather flagged z columns into compact k-major matrix ----
__global__ void __launch_bounds__(256)
gather_kernel(const float* __restrict__ z)
{
    const int cnt = g_flagcnt;
    const int tid = threadIdx.x;
    for (int slot = blockIdx.x; slot < cnt; slot += gridDim.x) {
        int meta = g_flaglist[slot];
        int b = meta >> 16, l = meta & 0xFFFF;
        g_zg[(size_t)tid * CAPROW + slot] = z[((size_t)b * D_ + tid) * L_ + l];
        g_zg[(size_t)(tid + 256) * CAPROW + slot] =
            z[((size_t)b * D_ + tid + 256) * L_ + l];
    }
}

// ---- exact fp32 rescan of flagged columns ----
__global__ void __launch_bounds__(256)
rescan_kernel(const float* __restrict__ W)
{
    __shared__ float Ws[32][128];
    __shared__ float Zs[32][RLT];
    __shared__ float pv[32][RLT];
    __shared__ int   pi[32][RLT];

    const int tid = threadIdx.x;
    const int tx = tid & 7, ty = tid >> 3;
    const int cnt = g_flagcnt;
    const int tiles = (cnt + RLT - 1) / RLT;

    for (int item = blockIdx.x; item < tiles * NSLICE; item += gridDim.x) {
        const int ct = item / NSLICE, ns = item % NSLICE;
        const int cb = ct * RLT, nb = ns * 128;

        float acc[4][8];
        #pragma unroll
        for (int i = 0; i < 4; ++i)
            #pragma unroll
            for (int j = 0; j < 8; ++j) acc[i][j] = 0.0f;

        for (int kc = 0; kc < 16; ++kc) {
            const int kb = kc * 32;
            __syncthreads();
            #pragma unroll
            for (int p = 0; p < 4; ++p) {
                int v = tid + p * 256;
                int n = v >> 3, kq = v & 7;
                float4 wv = *reinterpret_cast<const float4*>(
                    &W[(size_t)(nb + n) * D_ + kb + kq * 4]);
                Ws[kq * 4 + 0][n] = wv.x;
                Ws[kq * 4 + 1][n] = wv.y;
                Ws[kq * 4 + 2][n] = wv.z;
                Ws[kq * 4 + 3][n] = wv.w;
            }
            #pragma unroll
            for (int p = 0; p < 2; ++p) {
                int v = tid + p * 256;
                int kr = v >> 4, cq = v & 15;
                float4 zv = *reinterpret_cast<const float4*>(
                    &g_zg[(size_t)(kb + kr) * CAPROW + cb + cq * 4]);
                *reinterpret_cast<float4*>(&Zs[kr][cq * 4]) = zv;
            }
            __syncthreads();
            #pragma unroll
            for (int k = 0; k < 32; ++k) {
                float4 wa = *reinterpret_cast<const float4*>(&Ws[k][ty * 4]);
                float4 za = *reinterpret_cast<const float4*>(&Zs[k][tx * 8]);
                float4 zc = *reinterpret_cast<const float4*>(&Zs[k][tx * 8 + 4]);
                float wf[4] = {wa.x, wa.y, wa.z, wa.w};
                float zf[8] = {za.x, za.y, za.z, za.w, zc.x, zc.y, zc.z, zc.w};
                #pragma unroll
                for (int i = 0; i < 4; ++i)
                    #pragma unroll
                    for (int j = 0; j < 8; ++j)
                        acc[i][j] = fmaf(wf[i], zf[j], acc[i][j]);
            }
        }
        __syncthreads();
        #pragma unroll
        for (int j = 0; j < 8; ++j) {
            float m = acc[0][j];
            int mi = nb + ty * 4;
            #pragma unroll
            for (int i = 1; i < 4; ++i) {
                float v = acc[i][j];
                if (v > m) { m = v; mi = nb + ty * 4 + i; }
            }
            pv[ty][tx * 8 + j] = m;
            pi[ty][tx * 8 + j] = mi;
        }
        __syncthreads();
        if (tid < RLT) {
            float m = pv[0][tid]; int mi = pi[0][tid];
            #pragma unroll
            for (int r = 1; r < 32; ++r) {
                float v = pv[r][tid]; int vi = pi[r][tid];
                if (v > m || (v == m && vi < mi)) { m = v; mi = vi; }
            }
            g_rpv[ns][cb + tid] = m;
            g_rpi[ns][cb + tid] = mi;
        }
        __syncthreads();
    }
}

__global__ void __launch_bounds__(256)
flagmerge_kernel()
{
    const int cnt = g_flagcnt;
    for (int s = blockIdx.x * blockDim.x + threadIdx.x; s < cnt;
         s += gridDim.x * blockDim.x) {
        float bv = g_rpv[0][s]; int bi = g_rpi[0][s];
        #pragma unroll
        for (int r = 1; r < NSLICE; ++r) {
            float v = g_rpv[r][s];
            if (v > bv) { bv = v; bi = g_rpi[r][s]; }
        }
        int meta = g_flaglist[s];
        g_best[(meta >> 16) * L_ + (meta & 0xFFFF)] = bi;
    }
}

// ---- output: ind + z_q gather (smem-staged W) + loss ----
#define OW_SMEM (256 * 65 * 4)
__global__ void __launch_bounds__(256)
output_kernel(const float* __restrict__ z, const float* __restrict__ W,
              float* __restrict__ out)
{
    extern __shared__ float sw[];          // [256][65]
    __shared__ int besti[256];
    __shared__ double red[256];
    const int tid = threadIdx.x, lane = tid & 31, w = tid >> 5;
    const int b = blockIdx.x / 12, lt = blockIdx.x % 12;
    const int lbase = lt * 256;
    const int valid = (L_ - lbase < 256) ? (L_ - lbase) : 256;

    if (tid < 256) {
        int bi = 0;
        if (tid < valid) {
            bi = g_best[b * L_ + lbase + tid];
            out[ZQ_ELEMS + (size_t)b * L_ + lbase + tid] = (float)bi;
        }
        besti[tid] = bi;
    }
    __syncthreads();

    const float* zb = z + (size_t)b * D_ * L_;
    double lsum = 0.0;

    for (int dc = 0; dc < 8; ++dc) {
        const int d0 = dc * 64;
        // stage: warp w loads W rows for cols [w*32, w*32+32), coalesced
        #pragma unroll
        for (int cs = 0; cs < 32; ++cs) {
            int col = w * 32 + cs;
            const float2 wv = *reinterpret_cast<const float2*>(
                &W[(size_t)besti[col] * D_ + d0 + lane * 2]);
            sw[col * 65 + lane * 2]     = wv.x;
            sw[col * 65 + lane * 2 + 1] = wv.y;
        }
        __syncthreads();
        // write: col fastest -> coalesced stores + z reads
        #pragma unroll 4
        for (int it = 0; it < 64; ++it) {
            int idx = it * 256 + tid;
            int col = idx & 255;
            int dl = idx >> 8;
            if (col < valid) {
                int l = lbase + col;
                int d = d0 + dl;
                float wv = sw[col * 65 + dl];
                float zv = zb[(size_t)d * L_ + l];
                out[((size_t)b * D_ + d) * L_ + l] = wv;
                float df = wv - zv;
                lsum += (double)df * (double)df;
            }
        }
        __syncthreads();
    }

    red[tid] = lsum;
    __syncthreads();
    #pragma unroll
    for (int s = 128; s > 0; s >>= 1) {
        if (tid < s) red[tid] += red[tid + s];
        __syncthreads();
    }
    if (tid == 0) atomicAdd(&g_loss, red[0]);
}

extern "C" void kernel_launch(void* const* d_in, const int* in_sizes, int n_in,
                              void* d_out, int out_size) {
    const float* z = (const float*)d_in[0];
    const float* W = (const float*)d_in[1];
    if (n_in >= 2 && in_sizes[0] == NE_ * D_) {
        z = (const float*)d_in[1];
        W = (const float*)d_in[0];
    }
    float* out = (float*)d_out;

    cudaFuncSetAttribute(screen_kernel,
                         cudaFuncAttributeMaxDynamicSharedMemorySize, SMEM_SCREEN);
    cudaFuncSetAttribute(output_kernel,
                         cudaFuncAttributeMaxDynamicSharedMemorySize, OW_SMEM);

    init_kernel<<<1, 1>>>();
    convert_w_kernel<<<(NE_ * D_ / 4 + 255) / 256, 256>>>(W);
    convert_z_kernel<<<((int)(ZQ_ELEMS / 4) + 255) / 256, 256>>>(z);
    {
        dim3 grd((L_ + 127) / 128, B_);
        screen_kernel<<<grd, 256, SMEM_SCREEN>>>();
    }
    gather_kernel<<<256, 256>>>(z);
    rescan_kernel<<<512, 256>>>(W);
    flagmerge_kernel<<<64, 256>>>();
    output_kernel<<<B_ * 12, 256, OW_SMEM>>>(z, W, out);
    finalize_kernel<<<1, 1>>>(out);
}

// round 8
// speedup vs baseline: 4.5818x; 1.3329x over previous
#include <cuda_runtime.h>
#include <cstdint>

#define B_    16
#define D_    512
#define L_    3000
#define NE_   1024
#define LP    3072            // padded L per batch for partial arrays
#define ZQ_ELEMS  ((size_t)B_ * D_ * L_)
#define IND_ELEMS ((size_t)B_ * L_)

#define DELTA   0.25f         // bf16 screen margin (~11 sigma)
#define CAPROW  49152
#define NSLICE  8
#define RLT     64

// ---- device scratch (no allocation allowed anywhere) ----
__device__ __align__(16) unsigned short g_zb[(size_t)B_ * D_ * L_];
__device__ __align__(16) unsigned short g_wb[(size_t)NE_ * D_];
__device__ float  g_sv1[2][B_ * LP];
__device__ float  g_sv2[2][B_ * LP];
__device__ int    g_si1[2][B_ * LP];
__device__ int    g_best[B_ * L_];
__device__ float  g_blog[B_ * L_];     // best logit (bf16-acc or exact)
__device__ float  g_zsq[B_ * L_];
__device__ float  g_wsq[NE_];
__device__ int    g_flagcnt;
__device__ int    g_flaglist[CAPROW];
__device__ float  g_zg[(size_t)D_ * CAPROW];
__device__ float  g_rpv[NSLICE][CAPROW];
__device__ int    g_rpi[NSLICE][CAPROW];
__device__ double g_loss;

__device__ __forceinline__ uint32_t smem_u32(const void* p) {
    uint32_t a;
    asm("{ .reg .u64 t; cvta.to.shared.u64 t, %1; cvt.u32.u64 %0, t; }" : "=r"(a) : "l"(p));
    return a;
}
__device__ __forceinline__ unsigned short f2bf(float f) {   // RN-even
    uint32_t u = __float_as_uint(f);
    return (unsigned short)((u + 0x7FFFu + ((u >> 16) & 1u)) >> 16);
}

#define MMA_BF16(d, a, bb)                                                     \
    asm volatile("mma.sync.aligned.m16n8k16.row.col.f32.bf16.bf16.f32 "        \
        "{%0,%1,%2,%3}, {%4,%5,%6,%7}, {%8,%9}, {%0,%1,%2,%3};"                \
        : "+f"((d)[0]), "+f"((d)[1]), "+f"((d)[2]), "+f"((d)[3])               \
        : "r"((a)[0]), "r"((a)[1]), "r"((a)[2]), "r"((a)[3]),                  \
          "r"((bb)[0]), "r"((bb)[1]))

#define LDMX4(r, addr)                                                         \
    asm volatile("ldmatrix.sync.aligned.m8n8.x4.shared.b16 {%0,%1,%2,%3}, [%4];" \
        : "=r"((r)[0]), "=r"((r)[1]), "=r"((r)[2]), "=r"((r)[3]) : "r"(addr))

#define LDMX2T(r, addr)                                                        \
    asm volatile("ldmatrix.sync.aligned.m8n8.x2.trans.shared.b16 {%0,%1}, [%2];" \
        : "=r"((r)[0]), "=r"((r)[1]) : "r"(addr))

// ---- small kernels ----
__global__ void init_kernel() { g_loss = 0.0; g_flagcnt = 0; }

__global__ void finalize_kernel(float* __restrict__ out) {
    out[ZQ_ELEMS + IND_ELEMS] = (float)(2.25 * g_loss / ((double)B_ * D_ * L_));
}

// W -> bf16 + per-code sum of squares
__global__ void __launch_bounds__(128)
convert_w_kernel(const float* __restrict__ W) {
    __shared__ float red[4];
    const int n = blockIdx.x, tid = threadIdx.x;
    const size_t base = (size_t)n * D_ + tid * 4;
    float4 v = *reinterpret_cast<const float4*>(W + base);
    uint2 o;
    o.x = (uint32_t)f2bf(v.x) | ((uint32_t)f2bf(v.y) << 16);
    o.y = (uint32_t)f2bf(v.z) | ((uint32_t)f2bf(v.w) << 16);
    *reinterpret_cast<uint2*>(g_wb + base) = o;
    float s = v.x * v.x + v.y * v.y + v.z * v.z + v.w * v.w;
    #pragma unroll
    for (int off = 16; off > 0; off >>= 1) s += __shfl_xor_sync(~0u, s, off);
    if ((tid & 31) == 0) red[tid >> 5] = s;
    __syncthreads();
    if (tid == 0) g_wsq[n] = red[0] + red[1] + red[2] + red[3];
}

// z -> bf16 + per-column sum of squares (CTA = 128 cols of one batch)
__global__ void __launch_bounds__(128)
convert_z_kernel(const float* __restrict__ z) {
    const int tid = threadIdx.x;
    const int b = blockIdx.y, lb = blockIdx.x * 128;
    const int col = lb + tid;
    const bool valid = col < L_;
    const float* zp = z + (size_t)b * D_ * L_ + col;
    unsigned short* zo = g_zb + (size_t)b * D_ * L_ + col;
    float acc = 0.0f;
    #pragma unroll 8
    for (int d = 0; d < D_; ++d) {
        float v = valid ? zp[(size_t)d * L_] : 0.0f;
        if (valid) zo[(size_t)d * L_] = f2bf(v);
        acc = fmaf(v, v, acc);
    }
    if (valid) g_zsq[b * L_ + col] = acc;
}

// =====================================================================
// Screen half: 512 codes (4 supertiles) x 128 cols; bf16 mma m16n8k16;
// K-chunk 64, 3-stage cp.async ring, one __syncthreads per k-iter.
// =====================================================================
#define AST   18432            // 128 * 144
#define BST   17408            // 64 * 272
#define BOFF  (3 * AST)
#define EOFF  (3 * (AST + BST))
#define SMEM_SCREEN (EOFF + 4608)

__device__ __forceinline__ void screen_issue(
    const unsigned short* __restrict__ zrow,
    uint32_t sbase, int t, int tid, int lb, int halfrow)
{
    const int nsup = t >> 3;
    const int kb = (t & 7) * 64;
    const int st = t % 3;
    #pragma unroll
    for (int i = 0; i < 4; ++i) {            // A: 128 rows x 8 chunks(16B)
        int v = tid + i * 256;
        int row = v >> 3, ch = v & 7;
        uint32_t dst = sbase + st * AST + row * 144 + ch * 16;
        const unsigned short* src =
            g_wb + (size_t)(halfrow + nsup * 128 + row) * D_ + kb + ch * 8;
        asm volatile("cp.async.cg.shared.global [%0], [%1], 16;"
                     :: "r"(dst), "l"(src) : "memory");
    }
    #pragma unroll
    for (int i = 0; i < 4; ++i) {            // B: 64 k-rows x 16 chunks
        int v = tid + i * 256;
        int kr = v >> 4, ch = v & 15;
        uint32_t dst = sbase + BOFF + st * BST + kr * 272 + ch * 16;
        const unsigned short* src = zrow + (size_t)(kb + kr) * L_ + lb + ch * 8;
        uint32_t ssz = (lb + ch * 8 < L_) ? 16u : 0u;
        asm volatile("cp.async.cg.shared.global [%0], [%1], 16, %2;"
                     :: "r"(dst), "l"(src), "r"(ssz) : "memory");
    }
    asm volatile("cp.async.commit_group;" ::: "memory");
}

__global__ void __launch_bounds__(256, 2)
screen_kernel()
{
    extern __shared__ char smc[];
    const uint32_t sbase = smem_u32(smc);
    float* ep  = (float*)(smc + EOFF);
    float* wv1 = ep;                 // [2][128]
    float* wv2 = ep + 256;
    int*   wi1 = (int*)(ep + 512);
    float* rv1 = ep + 768;
    float* rv2 = ep + 896;
    int*   ri1 = (int*)(ep + 1024);

    const int tid = threadIdx.x, lane = tid & 31, w = tid >> 5;
    const int mw = w >> 2, nw = w & 3;
    const int g = lane >> 2, cth = lane & 3;
    const int b = blockIdx.y, lb = blockIdx.x * 128;
    const int half = blockIdx.z;
    const int halfrow = half * 512;
    const unsigned short* zrow = g_zb + (size_t)b * D_ * L_;

    if (tid < 128) { rv1[tid] = -3.0e38f; rv2[tid] = -3.0e38f; ri1[tid] = 0; }

    const uint32_t offA = (uint32_t)((lane & 15) * 144 + (lane >> 4) * 16);
    const uint32_t offB = (uint32_t)((lane & 15) * 272);

    float c[4][4][4];

    screen_issue(zrow, sbase, 0, tid, lb, halfrow);
    screen_issue(zrow, sbase, 1, tid, lb, halfrow);

    for (int t = 0; t < 32; ++t) {
        const int kc = t & 7, nsup = t >> 3, st = t % 3;

        if (t < 30) asm volatile("cp.async.wait_group 1;" ::: "memory");
        else        asm volatile("cp.async.wait_group 0;" ::: "memory");
        __syncthreads();
        if (t < 30) screen_issue(zrow, sbase, t + 2, tid, lb, halfrow);

        if (kc == 0) {
            #pragma unroll
            for (int mt = 0; mt < 4; ++mt)
                #pragma unroll
                for (int nt = 0; nt < 4; ++nt)
                    #pragma unroll
                    for (int r = 0; r < 4; ++r) c[mt][nt][r] = 0.0f;
        }

        const uint32_t aB = sbase + st * AST;
        const uint32_t bB = sbase + BOFF + st * BST;
        #pragma unroll
        for (int q = 0; q < 4; ++q) {
            uint32_t af[4][4], bf[4][2];
            #pragma unroll
            for (int mt = 0; mt < 4; ++mt)
                LDMX4(af[mt], aB + (uint32_t)((mw * 64 + mt * 16) * 144 + q * 32) + offA);
            #pragma unroll
            for (int nt = 0; nt < 4; ++nt)
                LDMX2T(bf[nt], bB + (uint32_t)(q * 16 * 272 + nw * 64 + nt * 16) + offB);
            #pragma unroll
            for (int mt = 0; mt < 4; ++mt)
                #pragma unroll
                for (int nt = 0; nt < 4; ++nt)
                    MMA_BF16(c[mt][nt], af[mt], bf[nt]);
        }

        if (kc == 7) {
            // ---- supertile epilogue: per-column top-2 ----
            #pragma unroll
            for (int nt = 0; nt < 4; ++nt) {
                #pragma unroll
                for (int p = 0; p < 2; ++p) {
                    float v1 = -3.0e38f, v2 = -3.0e38f; int i1 = 0;
                    #pragma unroll
                    for (int mt = 0; mt < 4; ++mt)
                        #pragma unroll
                        for (int r = 0; r < 2; ++r) {
                            float v = c[mt][nt][r * 2 + p];
                            int code = halfrow + nsup * 128 + mw * 64 + mt * 16 + r * 8 + g;
                            if (v > v1) { v2 = v1; v1 = v; i1 = code; }
                            else if (v > v2) v2 = v;
                        }
                    #pragma unroll
                    for (int off = 4; off < 32; off <<= 1) {
                        float ov1 = __shfl_xor_sync(~0u, v1, off);
                        float ov2 = __shfl_xor_sync(~0u, v2, off);
                        int   oi1 = __shfl_xor_sync(~0u, i1, off);
                        if (ov1 > v1) { v2 = fmaxf(v1, ov2); v1 = ov1; i1 = oi1; }
                        else          { v2 = fmaxf(v2, ov1); }
                    }
                    if (g == 0) {
                        int col = nw * 32 + nt * 8 + 2 * cth + p;
                        wv1[mw * 128 + col] = v1;
                        wv2[mw * 128 + col] = v2;
                        wi1[mw * 128 + col] = i1;
                    }
                }
            }
            __syncthreads();
            if (tid < 128) {
                float a1 = wv1[tid], a2 = wv2[tid];             int ai = wi1[tid];
                float b1 = wv1[128 + tid], b2 = wv2[128 + tid]; int bi = wi1[128 + tid];
                float m1, m2; int mi;
                if (a1 >= b1) { m1 = a1; mi = ai; m2 = fmaxf(a2, b1); }
                else          { m1 = b1; mi = bi; m2 = fmaxf(b2, a1); }
                if (m1 > rv1[tid]) {
                    rv2[tid] = fmaxf(rv1[tid], m2);
                    rv1[tid] = m1; ri1[tid] = mi;
                } else {
                    rv2[tid] = fmaxf(rv2[tid], m1);
                }
            }
            __syncthreads();
        }
    }

    if (tid < 128) {
        int idx = b * LP + lb + tid;
        g_sv1[half][idx] = rv1[tid];
        g_sv2[half][idx] = rv2[tid];
        g_si1[half][idx] = ri1[tid];
    }
}

// ---- merge halves, flag narrow margins ----
__global__ void __launch_bounds__(256)
select_kernel()
{
    for (int s = blockIdx.x * blockDim.x + threadIdx.x; s < B_ * L_;
         s += gridDim.x * blockDim.x) {
        int b = s / L_, l = s % L_;
        int pidx = b * LP + l;
        float a1 = g_sv1[0][pidx], a2 = g_sv2[0][pidx]; int ai = g_si1[0][pidx];
        float b1 = g_sv1[1][pidx], b2 = g_sv2[1][pidx]; int bi = g_si1[1][pidx];
        float m1, m2; int mi;
        if (a1 >= b1) { m1 = a1; mi = ai; m2 = fmaxf(a2, b1); }
        else          { m1 = b1; mi = bi; m2 = fmaxf(b2, a1); }
        g_best[s] = mi;
        g_blog[s] = m1;
        if (m1 - m2 < DELTA) {
            int fs = atomicAdd(&g_flagcnt, 1);
            g_flaglist[fs] = (b << 16) | l;
        }
    }
}

// ---- gather flagged z columns into compact k-major matrix ----
__global__ void __launch_bounds__(256)
gather_kernel(const float* __restrict__ z)
{
    const int cnt = g_flagcnt;
    const int tid = threadIdx.x;
    for (int slot = blockIdx.x; slot < cnt; slot += gridDim.x) {
        int meta = g_flaglist[slot];
        int b = meta >> 16, l = meta & 0xFFFF;
        g_zg[(size_t)tid * CAPROW + slot] = z[((size_t)b * D_ + tid) * L_ + l];
        g_zg[(size_t)(tid + 256) * CAPROW + slot] =
            z[((size_t)b * D_ + tid + 256) * L_ + l];
    }
}

// ---- exact fp32 rescan of flagged columns ----
__global__ void __launch_bounds__(256)
rescan_kernel(const float* __restrict__ W)
{
    __shared__ float Ws[32][128];
    __shared__ float Zs[32][RLT];
    __shared__ float pv[32][RLT];
    __shared__ int   pi[32][RLT];

    const int tid = threadIdx.x;
    const int tx = tid & 7, ty = tid >> 3;
    const int cnt = g_flagcnt;
    const int tiles = (cnt + RLT - 1) / RLT;

    for (int item = blockIdx.x; item < tiles * NSLICE; item += gridDim.x) {
        const int ct = item / NSLICE, ns = item % NSLICE;
        const int cb = ct * RLT, nb = ns * 128;

        float acc[4][8];
        #pragma unroll
        for (int i = 0; i < 4; ++i)
            #pragma unroll
            for (int j = 0; j < 8; ++j) acc[i][j] = 0.0f;

        for (int kc = 0; kc < 16; ++kc) {
            const int kb = kc * 32;
            __syncthreads();
            #pragma unroll
            for (int p = 0; p < 4; ++p) {
                int v = tid + p * 256;
                int n = v >> 3, kq = v & 7;
                float4 wv = *reinterpret_cast<const float4*>(
                    &W[(size_t)(nb + n) * D_ + kb + kq * 4]);
                Ws[kq * 4 + 0][n] = wv.x;
                Ws[kq * 4 + 1][n] = wv.y;
                Ws[kq * 4 + 2][n] = wv.z;
                Ws[kq * 4 + 3][n] = wv.w;
            }
            #pragma unroll
            for (int p = 0; p < 2; ++p) {
                int v = tid + p * 256;
                int kr = v >> 4, cq = v & 15;
                float4 zv = *reinterpret_cast<const float4*>(
                    &g_zg[(size_t)(kb + kr) * CAPROW + cb + cq * 4]);
                *reinterpret_cast<float4*>(&Zs[kr][cq * 4]) = zv;
            }
            __syncthreads();
            #pragma unroll
            for (int k = 0; k < 32; ++k) {
                float4 wa = *reinterpret_cast<const float4*>(&Ws[k][ty * 4]);
                float4 za = *reinterpret_cast<const float4*>(&Zs[k][tx * 8]);
                float4 zc = *reinterpret_cast<const float4*>(&Zs[k][tx * 8 + 4]);
                float wf[4] = {wa.x, wa.y, wa.z, wa.w};
                float zf[8] = {za.x, za.y, za.z, za.w, zc.x, zc.y, zc.z, zc.w};
                #pragma unroll
                for (int i = 0; i < 4; ++i)
                    #pragma unroll
                    for (int j = 0; j < 8; ++j)
                        acc[i][j] = fmaf(wf[i], zf[j], acc[i][j]);
            }
        }
        __syncthreads();
        #pragma unroll
        for (int j = 0; j < 8; ++j) {
            float m = acc[0][j];
            int mi = nb + ty * 4;
            #pragma unroll
            for (int i = 1; i < 4; ++i) {
                float v = acc[i][j];
                if (v > m) { m = v; mi = nb + ty * 4 + i; }
            }
            pv[ty][tx * 8 + j] = m;
            pi[ty][tx * 8 + j] = mi;
        }
        __syncthreads();
        if (tid < RLT) {
            float m = pv[0][tid]; int mi = pi[0][tid];
            #pragma unroll
            for (int r = 1; r < 32; ++r) {
                float v = pv[r][tid]; int vi = pi[r][tid];
                if (v > m || (v == m && vi < mi)) { m = v; mi = vi; }
            }
            g_rpv[ns][cb + tid] = m;
            g_rpi[ns][cb + tid] = mi;
        }
        __syncthreads();
    }
}

__global__ void __launch_bounds__(256)
flagmerge_kernel()
{
    const int cnt = g_flagcnt;
    for (int s = blockIdx.x * blockDim.x + threadIdx.x; s < cnt;
         s += gridDim.x * blockDim.x) {
        float bv = g_rpv[0][s]; int bi = g_rpi[0][s];
        #pragma unroll
        for (int r = 1; r < NSLICE; ++r) {
            float v = g_rpv[r][s];
            if (v > bv) { bv = v; bi = g_rpi[r][s]; }
        }
        int meta = g_flaglist[s];
        int bl = (meta >> 16) * L_ + (meta & 0xFFFF);
        g_best[bl] = bi;
        g_blog[bl] = bv;       // exact fp32 logit for flagged columns
    }
}

// ---- output: ind + z_q gather (smem-staged W), no z read ----
#define OW_SMEM (256 * 65 * 4)
__global__ void __launch_bounds__(256)
output_kernel(const float* __restrict__ W, float* __restrict__ out)
{
    extern __shared__ float sw[];          // [256][65]
    __shared__ int besti[256];
    const int tid = threadIdx.x, lane = tid & 31, w = tid >> 5;
    const int b = blockIdx.x / 12, lt = blockIdx.x % 12;
    const int lbase = lt * 256;
    const int valid = (L_ - lbase < 256) ? (L_ - lbase) : 256;

    {
        int bi = 0;
        if (tid < valid) {
            bi = g_best[b * L_ + lbase + tid];
            out[ZQ_ELEMS + (size_t)b * L_ + lbase + tid] = (float)bi;
        }
        besti[tid] = bi;
    }
    __syncthreads();

    for (int dc = 0; dc < 8; ++dc) {
        const int d0 = dc * 64;
        #pragma unroll
        for (int cs = 0; cs < 32; ++cs) {
            int col = w * 32 + cs;
            const float2 wv = *reinterpret_cast<const float2*>(
                &W[(size_t)besti[col] * D_ + d0 + lane * 2]);
            sw[col * 65 + lane * 2]     = wv.x;
            sw[col * 65 + lane * 2 + 1] = wv.y;
        }
        __syncthreads();
        #pragma unroll 8
        for (int it = 0; it < 64; ++it) {
            int idx = it * 256 + tid;
            int col = idx & 255;
            int dl = idx >> 8;
            if (col < valid) {
                out[((size_t)b * D_ + d0 + dl) * L_ + lbase + col] =
                    sw[col * 65 + dl];
            }
        }
        __syncthreads();
    }
}

// ---- loss via identity: wsq[ind] - 2*logit + zsq ----
__global__ void __launch_bounds__(256)
loss_kernel()
{
    __shared__ double red[256];
    const int tid = threadIdx.x;
    double lsum = 0.0;
    for (int s = blockIdx.x * blockDim.x + tid; s < B_ * L_;
         s += gridDim.x * blockDim.x) {
        lsum += (double)g_wsq[g_best[s]] - 2.0 * (double)g_blog[s]
              + (double)g_zsq[s];
    }
    red[tid] = lsum;
    __syncthreads();
    #pragma unroll
    for (int s = 128; s > 0; s >>= 1) {
        if (tid < s) red[tid] += red[tid + s];
        __syncthreads();
    }
    if (tid == 0) atomicAdd(&g_loss, red[0]);
}

extern "C" void kernel_launch(void* const* d_in, const int* in_sizes, int n_in,
                              void* d_out, int out_size) {
    const float* z = (const float*)d_in[0];
    const float* W = (const float*)d_in[1];
    if (n_in >= 2 && in_sizes[0] == NE_ * D_) {
        z = (const float*)d_in[1];
        W = (const float*)d_in[0];
    }
    float* out = (float*)d_out;

    cudaFuncSetAttribute(screen_kernel,
                         cudaFuncAttributeMaxDynamicSharedMemorySize, SMEM_SCREEN);
    cudaFuncSetAttribute(output_kernel,
                         cudaFuncAttributeMaxDynamicSharedMemorySize, OW_SMEM);

    init_kernel<<<1, 1>>>();
    convert_w_kernel<<<NE_, 128>>>(W);
    {
        dim3 grd((L_ + 127) / 128, B_);
        convert_z_kernel<<<grd, 128>>>(z);
    }
    {
        dim3 grd((L_ + 127) / 128, B_, 2);
        screen_kernel<<<grd, 256, SMEM_SCREEN>>>();
    }
    select_kernel<<<96, 256>>>();
    gather_kernel<<<256, 256>>>(z);
    rescan_kernel<<<512, 256>>>(W);
    flagmerge_kernel<<<64, 256>>>();
    output_kernel<<<B_ * 12, 256, OW_SMEM>>>(W, out);
    loss_kernel<<<96, 256>>>();
    finalize_kernel<<<1, 1>>>(out);
}